// round 2
// baseline (speedup 1.0000x reference)
#include <cuda_runtime.h>
#include <math.h>

#define Bq  4
#define Tq  1024
#define Dq  512
#define Hq  8
#define DHq 512
#define Lq  4
#define Vq  32000
#define Nrows (Bq*Tq)   // 4096

// ---- scratch (device globals; no allocation allowed) ----
__device__ float g_x[Nrows*Dq];            // residual stream
__device__ float g_h[Nrows*Dq];            // post-LN1
__device__ float g_f[Nrows*Dq];            // ffn hidden
__device__ float g_t[Nrows*Dq];            // attn_out / ffn out
__device__ float g_q[Hq*Nrows*DHq];        // [H,B,T,DH]
__device__ float g_k[Hq*Nrows*DHq];
__device__ float g_v[Hq*Nrows*DHq];
__device__ float g_s[(size_t)Hq*Bq*Tq*Tq]; // [H,B,T,T] scores/probs
__device__ float g_o[(size_t)Nrows*Hq*DHq];// [B,T,H*DH] concat heads

// ---------------------------------------------------------------------------
// Embedding: x[n,d] = tok_emb[idx[n],d] + pos_emb[n%T,d]
// ---------------------------------------------------------------------------
__global__ void embed_kernel(const int* __restrict__ idx,
                             const float* __restrict__ tok,
                             const float* __restrict__ pos,
                             float* __restrict__ x) {
    int row = blockIdx.x;
    int t = row % Tq;
    int v = idx[row];
    const float4* te = (const float4*)(tok + (long)v * Dq);
    const float4* pe = (const float4*)(pos + (long)t * Dq);
    float4* xo = (float4*)(x + (long)row * Dq);
    for (int i = threadIdx.x; i < Dq / 4; i += blockDim.x) {
        float4 a = te[i], b = pe[i];
        xo[i] = make_float4(a.x + b.x, a.y + b.y, a.z + b.z, a.w + b.w);
    }
}

// ---------------------------------------------------------------------------
// Generic batched SGEMM: C = alpha * A @ B (+ bias) [+ relu]
//   A: [M,K] row-major, lda = K, per-batch offset = batch*sA
//   B: NN -> [K,N] ldb,  NT -> [N,K] ldb (computes A @ B^T)
//   C: per-batch offset = (batch/innerCount)*oCout + (batch%innerCount)*oCin
//   All M,N multiples of 64; K multiple of 16 (guaranteed by problem shapes).
// ---------------------------------------------------------------------------
template <bool TB, bool RELU>
__global__ __launch_bounds__(256)
void gemm_kernel(const float* __restrict__ A, const float* __restrict__ Bm,
                 const float* __restrict__ bias, float* __restrict__ C,
                 int K, int ldb, int ldc,
                 long sA, long sB, long oCout, long oCin, int innerCount,
                 float alpha) {
    __shared__ float As[16][68];
    __shared__ float Bs[16][68];

    int batch = blockIdx.z;
    const float* Ab = A + (long)batch * sA;
    const float* Bb = Bm + (long)batch * sB;
    float* Cb = C + (long)(batch / innerCount) * oCout
                  + (long)(batch % innerCount) * oCin;

    int mBase = blockIdx.y * 64;
    int nBase = blockIdx.x * 64;
    int tid = threadIdx.x;
    int tx = tid & 15, ty = tid >> 4;

    float acc[4][4] = {};

    for (int k0 = 0; k0 < K; k0 += 16) {
        // A tile 64x16 -> As[k][m]
        #pragma unroll
        for (int j = 0; j < 4; j++) {
            int l = tid + 256 * j;
            int r = l >> 4, c = l & 15;
            As[c][r] = Ab[(long)(mBase + r) * K + k0 + c];
        }
        if (TB) {
            // B is [N,K]: tile 64(n) x 16(k) -> Bs[k][n]
            #pragma unroll
            for (int j = 0; j < 4; j++) {
                int l = tid + 256 * j;
                int r = l >> 4, c = l & 15;
                Bs[c][r] = Bb[(long)(nBase + r) * ldb + k0 + c];
            }
        } else {
            // B is [K,N]: tile 16(k) x 64(n) -> Bs[k][n]
            #pragma unroll
            for (int j = 0; j < 4; j++) {
                int l = tid + 256 * j;
                int r = l >> 6, c = l & 63;
                Bs[r][c] = Bb[(long)(k0 + r) * ldb + nBase + c];
            }
        }
        __syncthreads();
        #pragma unroll
        for (int k = 0; k < 16; k++) {
            float4 a = *(const float4*)&As[k][ty * 4];
            float4 b = *(const float4*)&Bs[k][tx * 4];
            float av[4] = {a.x, a.y, a.z, a.w};
            float bv[4] = {b.x, b.y, b.z, b.w};
            #pragma unroll
            for (int i = 0; i < 4; i++)
                #pragma unroll
                for (int j = 0; j < 4; j++)
                    acc[i][j] += av[i] * bv[j];
        }
        __syncthreads();
    }

    #pragma unroll
    for (int i = 0; i < 4; i++) {
        int m = mBase + ty * 4 + i;
        int n = nBase + tx * 4;
        float4 r;
        r.x = acc[i][0] * alpha;
        r.y = acc[i][1] * alpha;
        r.z = acc[i][2] * alpha;
        r.w = acc[i][3] * alpha;
        if (bias) {
            r.x += bias[n];     r.y += bias[n + 1];
            r.z += bias[n + 2]; r.w += bias[n + 3];
        }
        if (RELU) {
            r.x = fmaxf(r.x, 0.f); r.y = fmaxf(r.y, 0.f);
            r.z = fmaxf(r.z, 0.f); r.w = fmaxf(r.w, 0.f);
        }
        *(float4*)(&Cb[(long)m * ldc + n]) = r;
    }
}

// ---------------------------------------------------------------------------
// Row softmax over 1024 columns (in place). One block (256 thr) per row.
// ---------------------------------------------------------------------------
__global__ void softmax_kernel(float* __restrict__ S) {
    __shared__ float sred[8];
    float* p = S + (long)blockIdx.x * Tq;
    int tid = threadIdx.x;
    float4 v = ((const float4*)p)[tid];

    float m = fmaxf(fmaxf(v.x, v.y), fmaxf(v.z, v.w));
    #pragma unroll
    for (int o = 16; o; o >>= 1) m = fmaxf(m, __shfl_xor_sync(0xffffffffu, m, o));
    if ((tid & 31) == 0) sred[tid >> 5] = m;
    __syncthreads();
    if (tid < 32) {
        float t = (tid < 8) ? sred[tid] : -1e30f;
        #pragma unroll
        for (int o = 16; o; o >>= 1) t = fmaxf(t, __shfl_xor_sync(0xffffffffu, t, o));
        if (tid == 0) sred[0] = t;
    }
    __syncthreads();
    m = sred[0];
    __syncthreads();

    v.x = __expf(v.x - m); v.y = __expf(v.y - m);
    v.z = __expf(v.z - m); v.w = __expf(v.w - m);
    float s = v.x + v.y + v.z + v.w;
    #pragma unroll
    for (int o = 16; o; o >>= 1) s += __shfl_xor_sync(0xffffffffu, s, o);
    if ((tid & 31) == 0) sred[tid >> 5] = s;
    __syncthreads();
    if (tid < 32) {
        float t = (tid < 8) ? sred[tid] : 0.f;
        #pragma unroll
        for (int o = 16; o; o >>= 1) t += __shfl_xor_sync(0xffffffffu, t, o);
        if (tid == 0) sred[0] = t;
    }
    __syncthreads();
    float inv = 1.0f / sred[0];
    v.x *= inv; v.y *= inv; v.z *= inv; v.w *= inv;
    ((float4*)p)[tid] = v;
}

// ---------------------------------------------------------------------------
// out = LayerNorm(a + b) * g + be   (row = 512 elems, 128 thr x float4)
// Two-pass variance for numerical safety.
// ---------------------------------------------------------------------------
__global__ void add_ln_kernel(const float* __restrict__ a,
                              const float* __restrict__ b,
                              const float* __restrict__ g,
                              const float* __restrict__ be,
                              float* __restrict__ out) {
    __shared__ float sred[4];
    int row = blockIdx.x;
    int tid = threadIdx.x;  // 128
    float4 va = ((const float4*)(a + (long)row * Dq))[tid];
    float4 vb = ((const float4*)(b + (long)row * Dq))[tid];
    float4 v = make_float4(va.x + vb.x, va.y + vb.y, va.z + vb.z, va.w + vb.w);

    float s = v.x + v.y + v.z + v.w;
    #pragma unroll
    for (int o = 16; o; o >>= 1) s += __shfl_xor_sync(0xffffffffu, s, o);
    if ((tid & 31) == 0) sred[tid >> 5] = s;
    __syncthreads();
    float mean = (sred[0] + sred[1] + sred[2] + sred[3]) * (1.0f / Dq);
    __syncthreads();

    float dx = v.x - mean, dy = v.y - mean, dz = v.z - mean, dw = v.w - mean;
    float sq = dx * dx + dy * dy + dz * dz + dw * dw;
    #pragma unroll
    for (int o = 16; o; o >>= 1) sq += __shfl_xor_sync(0xffffffffu, sq, o);
    if ((tid & 31) == 0) sred[tid >> 5] = sq;
    __syncthreads();
    float var = (sred[0] + sred[1] + sred[2] + sred[3]) * (1.0f / Dq);
    float inv = rsqrtf(var + 1e-5f);

    float4 gg = ((const float4*)g)[tid];
    float4 bb = ((const float4*)be)[tid];
    float4 r;
    r.x = dx * inv * gg.x + bb.x;
    r.y = dy * inv * gg.y + bb.y;
    r.z = dz * inv * gg.z + bb.z;
    r.w = dw * inv * gg.w + bb.w;
    ((float4*)(out + (long)row * Dq))[tid] = r;
}

// ---------------------------------------------------------------------------
extern "C" void kernel_launch(void* const* d_in, const int* in_sizes, int n_in,
                              void* d_out, int out_size) {
    const int*   idx  = (const int*)  d_in[0];
    const float* tok  = (const float*)d_in[1];
    const float* pos  = (const float*)d_in[2];
    const float* Wq   = (const float*)d_in[3];
    const float* Wk   = (const float*)d_in[4];
    const float* Wv   = (const float*)d_in[5];
    const float* Wo   = (const float*)d_in[6];
    const float* bo   = (const float*)d_in[7];
    const float* ln1g = (const float*)d_in[8];
    const float* ln1b = (const float*)d_in[9];
    const float* ln2g = (const float*)d_in[10];
    const float* ln2b = (const float*)d_in[11];
    const float* W1   = (const float*)d_in[12];
    const float* b1   = (const float*)d_in[13];
    const float* W2   = (const float*)d_in[14];
    const float* b2   = (const float*)d_in[15];
    const float* lmw  = (const float*)d_in[16];
    const float* lmb  = (const float*)d_in[17];
    float* out = (float*)d_out;

    float *x, *h, *f, *t, *q, *k, *v, *s, *o;
    cudaGetSymbolAddress((void**)&x, g_x);
    cudaGetSymbolAddress((void**)&h, g_h);
    cudaGetSymbolAddress((void**)&f, g_f);
    cudaGetSymbolAddress((void**)&t, g_t);
    cudaGetSymbolAddress((void**)&q, g_q);
    cudaGetSymbolAddress((void**)&k, g_k);
    cudaGetSymbolAddress((void**)&v, g_v);
    cudaGetSymbolAddress((void**)&s, g_s);
    cudaGetSymbolAddress((void**)&o, g_o);

    const float scale = 1.0f / sqrtf((float)DHq);

    embed_kernel<<<Nrows, 128>>>(idx, tok, pos, x);

    for (int l = 0; l < Lq; l++) {
        const float* wq = Wq + (long)l * Hq * Dq * DHq;
        const float* wk = Wk + (long)l * Hq * Dq * DHq;
        const float* wv = Wv + (long)l * Hq * Dq * DHq;
        const float* wo = Wo + (long)l * Hq * DHq * Dq;

        // Q/K/V: batched over heads. A = x (shared), B = W[l,h] (D x DH).
        dim3 gqkv(DHq / 64, Nrows / 64, Hq);
        gemm_kernel<false, false><<<gqkv, 256>>>(x, wq, nullptr, q,
            Dq, DHq, DHq, 0L, (long)Dq * DHq, (long)Nrows * DHq, 0L, 1, 1.0f);
        gemm_kernel<false, false><<<gqkv, 256>>>(x, wk, nullptr, k,
            Dq, DHq, DHq, 0L, (long)Dq * DHq, (long)Nrows * DHq, 0L, 1, 1.0f);
        gemm_kernel<false, false><<<gqkv, 256>>>(x, wv, nullptr, v,
            Dq, DHq, DHq, 0L, (long)Dq * DHq, (long)Nrows * DHq, 0L, 1, 1.0f);

        // scores = scale * Q @ K^T : 32 batches (h*B+b), [T,T]
        dim3 gs(Tq / 64, Tq / 64, Hq * Bq);
        gemm_kernel<true, false><<<gs, 256>>>(q, k, nullptr, s,
            DHq, DHq, Tq, (long)Tq * DHq, (long)Tq * DHq,
            (long)Tq * Tq, 0L, 1, scale);

        softmax_kernel<<<Hq * Bq * Tq, 256>>>(s);

        // O = P @ V, written directly into concat [B,T,H*DH]
        dim3 gav(DHq / 64, Tq / 64, Hq * Bq);
        gemm_kernel<false, false><<<gav, 256>>>(s, v, nullptr, o,
            Tq, DHq, Hq * DHq, (long)Tq * Tq, (long)Tq * DHq,
            (long)DHq /*per-h*/, (long)Tq * Hq * DHq /*per-b*/, Bq, 1.0f);

        // attn_out = O @ Wo + bo
        dim3 gwo(Dq / 64, Nrows / 64, 1);
        gemm_kernel<false, false><<<gwo, 256>>>(o, wo, bo + (long)l * Dq, t,
            Hq * DHq, Dq, Dq, 0L, 0L, 0L, 0L, 1, 1.0f);

        // h = LN(attn_out + x)
        add_ln_kernel<<<Nrows, 128>>>(t, x, ln1g + (long)l * Dq,
                                      ln1b + (long)l * Dq, h);

        // ffn
        dim3 gff(Dq / 64, Nrows / 64, 1);
        gemm_kernel<false, true><<<gff, 256>>>(h, W1 + (long)l * Dq * Dq,
            b1 + (long)l * Dq, f, Dq, Dq, Dq, 0L, 0L, 0L, 0L, 1, 1.0f);
        gemm_kernel<false, false><<<gff, 256>>>(f, W2 + (long)l * Dq * Dq,
            b2 + (long)l * Dq, t, Dq, Dq, Dq, 0L, 0L, 0L, 0L, 1, 1.0f);

        // x = LN(ff + x)   (residual from block INPUT x, per reference)
        add_ln_kernel<<<Nrows, 128>>>(t, x, ln2g + (long)l * Dq,
                                      ln2b + (long)l * Dq, x);
    }

    // logits = x @ lm_w + lm_b
    dim3 glm(Vq / 64, Nrows / 64, 1);
    gemm_kernel<false, false><<<glm, 256>>>(x, lmw, lmb, out,
        Dq, Vq, Vq, 0L, 0L, 0L, 0L, 1, 1.0f);
}

// round 6
// speedup vs baseline: 3.1587x; 3.1587x over previous
#include <cuda_runtime.h>
#include <cstdint>
#include <math.h>

#define Bq  4
#define Tq  1024
#define Dq  512
#define Hq  8
#define DHq 512
#define Lq  4
#define Vq  32000
#define Nrows (Bq*Tq)   // 4096

// ---- scratch (device globals; no allocation allowed) ----
__device__ float g_x[Nrows*Dq];
__device__ float g_h[Nrows*Dq];
__device__ float g_f[Nrows*Dq];
__device__ float g_t[Nrows*Dq];
__device__ float g_q[Hq*Nrows*DHq];              // [H,B*T,DH]
__device__ float g_k[Hq*Nrows*DHq];              // [H,B*T,DH]
__device__ float g_vt[Hq*(size_t)DHq*Nrows];     // [H,DH,B*T]  (V transposed)
__device__ float g_s[(size_t)Hq*Bq*Tq*Tq];       // [H*B,T,T]
__device__ float g_o[(size_t)Nrows*Hq*DHq];      // [B,T,H*DH]
// transposed weights (K-major NT operands everywhere)
__device__ float g_wqT[Lq*Hq*Dq*DHq];            // [L,H,DH,D]
__device__ float g_wkT[Lq*Hq*Dq*DHq];
__device__ float g_wvT[Lq*Hq*Dq*DHq];
__device__ float g_woT[Lq*Dq*Hq*DHq];            // [L,D,H*DH]
__device__ float g_w1T[Lq*Dq*Dq];
__device__ float g_w2T[Lq*Dq*Dq];
__device__ float g_lmwT[(size_t)Vq*Dq];          // [V,D]

// ===========================================================================
// TF32 helpers (sm_80-compatible; no sm_103a-only features)
// ===========================================================================
__device__ __forceinline__ float tf32r(float x) {
    uint32_t u;
    asm("cvt.rna.tf32.f32 %0, %1;" : "=r"(u) : "f"(x));
    return __uint_as_float(u);
}
__device__ __forceinline__ void mma_tf32(float* d, const uint32_t* a,
                                         const uint32_t* b) {
    asm volatile(
        "mma.sync.aligned.m16n8k8.row.col.f32.tf32.tf32.f32 "
        "{%0,%1,%2,%3}, {%4,%5,%6,%7}, {%8,%9}, {%0,%1,%2,%3};"
        : "+f"(d[0]), "+f"(d[1]), "+f"(d[2]), "+f"(d[3])
        : "r"(a[0]), "r"(a[1]), "r"(a[2]), "r"(a[3]), "r"(b[0]), "r"(b[1]));
}

// ===========================================================================
// TF32 HMMA GEMM:  C[M,N] = alpha * A[M,K] @ B[N,K]^T (+bias) (+relu)
//   A row-major lda, B row-major ldb (K contiguous), C row-major ldc.
//   Tile 128x128, K chunk = 32. 8 warps: 2(m) x 4(n); warp tile 64x32.
//   batch z: A += z*sA; B += (z/inB)*sBout + (z%inB)*sBin;
//            C += (z/inC)*oCout + (z%inC)*oCin
//   M%128==0, N%128==0, K%32==0.
// ===========================================================================
#define TILE_M 128
#define TILE_N 128
#define TILE_K 32
#define KSTR   36   // padded smem row stride (floats): (4*row + t) mod 32 = lane

__global__ __launch_bounds__(256)
void tgemm(const float* __restrict__ A, const float* __restrict__ B,
           const float* __restrict__ bias, float* __restrict__ C,
           int K, int lda, int ldb, int ldc,
           long sA, long sBout, long sBin, int inB,
           long oCout, long oCin, int inC,
           float alpha, int relu) {
    __shared__ float As[TILE_M * KSTR];
    __shared__ float Bs[TILE_N * KSTR];

    int tid = threadIdx.x;
    int lane = tid & 31;
    int wid = tid >> 5;
    int wm = (wid & 1) * 64;    // warp m offset
    int wn = (wid >> 1) * 32;   // warp n offset
    int g = lane >> 2, t = lane & 3;
    int z = blockIdx.z;

    const float* Ab = A + (long)blockIdx.y * TILE_M * lda + (long)z * sA;
    const float* Bb = B + (long)blockIdx.x * TILE_N * ldb
                        + (long)(z / inB) * sBout + (long)(z % inB) * sBin;
    float* Cb = C + (long)(z / inC) * oCout + (long)(z % inC) * oCin
                  + (long)blockIdx.y * TILE_M * ldc + (long)blockIdx.x * TILE_N;

    float acc[4][4][4];
#pragma unroll
    for (int i = 0; i < 4; i++)
#pragma unroll
        for (int j = 0; j < 4; j++)
#pragma unroll
            for (int r = 0; r < 4; r++) acc[i][j][r] = 0.f;

    float4 ra[4], rb[4];

    // prologue load chunk 0
#pragma unroll
    for (int j = 0; j < 4; j++) {
        int idx = tid + 256 * j;
        ra[j] = *(const float4*)(Ab + (long)(idx >> 3) * lda + ((idx & 7) << 2));
        rb[j] = *(const float4*)(Bb + (long)(idx >> 3) * ldb + ((idx & 7) << 2));
    }

    int nch = K / TILE_K;
    for (int c = 0; c < nch; c++) {
        __syncthreads();
        // store staged chunk with tf32 rounding
#pragma unroll
        for (int j = 0; j < 4; j++) {
            int idx = tid + 256 * j;
            int off = (idx >> 3) * KSTR + ((idx & 7) << 2);
            As[off + 0] = tf32r(ra[j].x); As[off + 1] = tf32r(ra[j].y);
            As[off + 2] = tf32r(ra[j].z); As[off + 3] = tf32r(ra[j].w);
            Bs[off + 0] = tf32r(rb[j].x); Bs[off + 1] = tf32r(rb[j].y);
            Bs[off + 2] = tf32r(rb[j].z); Bs[off + 3] = tf32r(rb[j].w);
        }
        __syncthreads();
        // prefetch next chunk
        if (c + 1 < nch) {
            int k0 = (c + 1) * TILE_K;
#pragma unroll
            for (int j = 0; j < 4; j++) {
                int idx = tid + 256 * j;
                ra[j] = *(const float4*)(Ab + (long)(idx >> 3) * lda + k0 + ((idx & 7) << 2));
                rb[j] = *(const float4*)(Bb + (long)(idx >> 3) * ldb + k0 + ((idx & 7) << 2));
            }
        }
        // compute current chunk: 4 k8 steps
#pragma unroll
        for (int ks = 0; ks < 4; ks++) {
            int kk = ks * 8;
            uint32_t af[4][4];
#pragma unroll
            for (int im = 0; im < 4; im++) {
                int row = wm + im * 16 + g;
                af[im][0] = __float_as_uint(As[row * KSTR + kk + t]);
                af[im][1] = __float_as_uint(As[(row + 8) * KSTR + kk + t]);
                af[im][2] = __float_as_uint(As[row * KSTR + kk + 4 + t]);
                af[im][3] = __float_as_uint(As[(row + 8) * KSTR + kk + 4 + t]);
            }
            uint32_t bf[4][2];
#pragma unroll
            for (int in = 0; in < 4; in++) {
                int n = wn + in * 8 + g;
                bf[in][0] = __float_as_uint(Bs[n * KSTR + kk + t]);
                bf[in][1] = __float_as_uint(Bs[n * KSTR + kk + 4 + t]);
            }
#pragma unroll
            for (int im = 0; im < 4; im++)
#pragma unroll
                for (int in = 0; in < 4; in++)
                    mma_tf32(acc[im][in], af[im], bf[in]);
        }
    }

    // epilogue
    int nBase = blockIdx.x * TILE_N;
#pragma unroll
    for (int im = 0; im < 4; im++) {
#pragma unroll
        for (int in = 0; in < 4; in++) {
            int r0 = wm + im * 16 + g;
            int cn = wn + in * 8 + t * 2;
            float2 v0, v1;
            v0.x = acc[im][in][0] * alpha;
            v0.y = acc[im][in][1] * alpha;
            v1.x = acc[im][in][2] * alpha;
            v1.y = acc[im][in][3] * alpha;
            if (bias) {
                float bx = bias[nBase + cn], by = bias[nBase + cn + 1];
                v0.x += bx; v0.y += by;
                v1.x += bx; v1.y += by;
            }
            if (relu) {
                v0.x = fmaxf(v0.x, 0.f); v0.y = fmaxf(v0.y, 0.f);
                v1.x = fmaxf(v1.x, 0.f); v1.y = fmaxf(v1.y, 0.f);
            }
            *(float2*)&Cb[(long)r0 * ldc + cn] = v0;
            *(float2*)&Cb[(long)(r0 + 8) * ldc + cn] = v1;
        }
    }
}

// ===========================================================================
// Transpose: out[z, c, r] = in[z, r, c].  R,C multiples of 32. block 32x8.
// ===========================================================================
__global__ void transpose_kernel(const float* __restrict__ in,
                                 float* __restrict__ out, int R, int C) {
    __shared__ float t[32][33];
    long zoff = (long)blockIdx.z * R * C;
    int c0 = blockIdx.x * 32, r0 = blockIdx.y * 32;
    int x = threadIdx.x, y = threadIdx.y;
#pragma unroll
    for (int j = 0; j < 32; j += 8)
        t[y + j][x] = in[zoff + (long)(r0 + y + j) * C + c0 + x];
    __syncthreads();
#pragma unroll
    for (int j = 0; j < 32; j += 8)
        out[zoff + (long)(c0 + y + j) * R + r0 + x] = t[x][y + j];
}

// ===========================================================================
// Embedding / softmax / add+LN
// ===========================================================================
__global__ void embed_kernel(const int* __restrict__ idx,
                             const float* __restrict__ tok,
                             const float* __restrict__ pos,
                             float* __restrict__ x) {
    int row = blockIdx.x;
    int t = row % Tq;
    int v = idx[row];
    const float4* te = (const float4*)(tok + (long)v * Dq);
    const float4* pe = (const float4*)(pos + (long)t * Dq);
    float4* xo = (float4*)(x + (long)row * Dq);
    for (int i = threadIdx.x; i < Dq / 4; i += blockDim.x) {
        float4 a = te[i], b = pe[i];
        xo[i] = make_float4(a.x + b.x, a.y + b.y, a.z + b.z, a.w + b.w);
    }
}

__global__ void softmax_kernel(float* __restrict__ S) {
    __shared__ float sred[8];
    float* p = S + (long)blockIdx.x * Tq;
    int tid = threadIdx.x;
    float4 v = ((const float4*)p)[tid];

    float m = fmaxf(fmaxf(v.x, v.y), fmaxf(v.z, v.w));
#pragma unroll
    for (int o = 16; o; o >>= 1) m = fmaxf(m, __shfl_xor_sync(0xffffffffu, m, o));
    if ((tid & 31) == 0) sred[tid >> 5] = m;
    __syncthreads();
    if (tid < 32) {
        float t = (tid < 8) ? sred[tid] : -1e30f;
#pragma unroll
        for (int o = 16; o; o >>= 1) t = fmaxf(t, __shfl_xor_sync(0xffffffffu, t, o));
        if (tid == 0) sred[0] = t;
    }
    __syncthreads();
    m = sred[0];
    __syncthreads();

    v.x = __expf(v.x - m); v.y = __expf(v.y - m);
    v.z = __expf(v.z - m); v.w = __expf(v.w - m);
    float s = v.x + v.y + v.z + v.w;
#pragma unroll
    for (int o = 16; o; o >>= 1) s += __shfl_xor_sync(0xffffffffu, s, o);
    if ((tid & 31) == 0) sred[tid >> 5] = s;
    __syncthreads();
    if (tid < 32) {
        float t = (tid < 8) ? sred[tid] : 0.f;
#pragma unroll
        for (int o = 16; o; o >>= 1) t += __shfl_xor_sync(0xffffffffu, t, o);
        if (tid == 0) sred[0] = t;
    }
    __syncthreads();
    float inv = 1.0f / sred[0];
    v.x *= inv; v.y *= inv; v.z *= inv; v.w *= inv;
    ((float4*)p)[tid] = v;
}

__global__ void add_ln_kernel(const float* __restrict__ a,
                              const float* __restrict__ b,
                              const float* __restrict__ g,
                              const float* __restrict__ be,
                              float* __restrict__ out) {
    __shared__ float sred[4];
    int row = blockIdx.x;
    int tid = threadIdx.x;  // 128
    float4 va = ((const float4*)(a + (long)row * Dq))[tid];
    float4 vb = ((const float4*)(b + (long)row * Dq))[tid];
    float4 v = make_float4(va.x + vb.x, va.y + vb.y, va.z + vb.z, va.w + vb.w);

    float s = v.x + v.y + v.z + v.w;
#pragma unroll
    for (int o = 16; o; o >>= 1) s += __shfl_xor_sync(0xffffffffu, s, o);
    if ((tid & 31) == 0) sred[tid >> 5] = s;
    __syncthreads();
    float mean = (sred[0] + sred[1] + sred[2] + sred[3]) * (1.0f / Dq);
    __syncthreads();

    float dx = v.x - mean, dy = v.y - mean, dz = v.z - mean, dw = v.w - mean;
    float sq = dx * dx + dy * dy + dz * dz + dw * dw;
#pragma unroll
    for (int o = 16; o; o >>= 1) sq += __shfl_xor_sync(0xffffffffu, sq, o);
    if ((tid & 31) == 0) sred[tid >> 5] = sq;
    __syncthreads();
    float var = (sred[0] + sred[1] + sred[2] + sred[3]) * (1.0f / Dq);
    float inv = rsqrtf(var + 1e-5f);

    float4 gg = ((const float4*)g)[tid];
    float4 bb = ((const float4*)be)[tid];
    float4 r;
    r.x = dx * inv * gg.x + bb.x;
    r.y = dy * inv * gg.y + bb.y;
    r.z = dz * inv * gg.z + bb.z;
    r.w = dw * inv * gg.w + bb.w;
    ((float4*)(out + (long)row * Dq))[tid] = r;
}

// ===========================================================================
extern "C" void kernel_launch(void* const* d_in, const int* in_sizes, int n_in,
                              void* d_out, int out_size) {
    const int*   idx  = (const int*)  d_in[0];
    const float* tok  = (const float*)d_in[1];
    const float* pos  = (const float*)d_in[2];
    const float* Wq   = (const float*)d_in[3];
    const float* Wk   = (const float*)d_in[4];
    const float* Wv   = (const float*)d_in[5];
    const float* Wo   = (const float*)d_in[6];
    const float* bo   = (const float*)d_in[7];
    const float* ln1g = (const float*)d_in[8];
    const float* ln1b = (const float*)d_in[9];
    const float* ln2g = (const float*)d_in[10];
    const float* ln2b = (const float*)d_in[11];
    const float* W1   = (const float*)d_in[12];
    const float* b1   = (const float*)d_in[13];
    const float* W2   = (const float*)d_in[14];
    const float* b2   = (const float*)d_in[15];
    const float* lmw  = (const float*)d_in[16];
    const float* lmb  = (const float*)d_in[17];
    float* out = (float*)d_out;

    float *x, *h, *f, *t, *q, *k, *vt, *s, *o;
    float *wqT, *wkT, *wvT, *woT, *w1T, *w2T, *lmwT;
    cudaGetSymbolAddress((void**)&x, g_x);
    cudaGetSymbolAddress((void**)&h, g_h);
    cudaGetSymbolAddress((void**)&f, g_f);
    cudaGetSymbolAddress((void**)&t, g_t);
    cudaGetSymbolAddress((void**)&q, g_q);
    cudaGetSymbolAddress((void**)&k, g_k);
    cudaGetSymbolAddress((void**)&vt, g_vt);
    cudaGetSymbolAddress((void**)&s, g_s);
    cudaGetSymbolAddress((void**)&o, g_o);
    cudaGetSymbolAddress((void**)&wqT, g_wqT);
    cudaGetSymbolAddress((void**)&wkT, g_wkT);
    cudaGetSymbolAddress((void**)&wvT, g_wvT);
    cudaGetSymbolAddress((void**)&woT, g_woT);
    cudaGetSymbolAddress((void**)&w1T, g_w1T);
    cudaGetSymbolAddress((void**)&w2T, g_w2T);
    cudaGetSymbolAddress((void**)&lmwT, g_lmwT);

    const float scale = 1.0f / sqrtf((float)DHq);
    dim3 tb(32, 8);

    // transpose all weights (K-major NT operands everywhere)
    transpose_kernel<<<dim3(DHq/32, Dq/32, Lq*Hq), tb>>>(Wq, wqT, Dq, DHq);
    transpose_kernel<<<dim3(DHq/32, Dq/32, Lq*Hq), tb>>>(Wk, wkT, Dq, DHq);
    transpose_kernel<<<dim3(DHq/32, Dq/32, Lq*Hq), tb>>>(Wv, wvT, Dq, DHq);
    transpose_kernel<<<dim3(Dq/32, (Hq*DHq)/32, Lq), tb>>>(Wo, woT, Hq*DHq, Dq);
    transpose_kernel<<<dim3(Dq/32, Dq/32, Lq), tb>>>(W1, w1T, Dq, Dq);
    transpose_kernel<<<dim3(Dq/32, Dq/32, Lq), tb>>>(W2, w2T, Dq, Dq);
    transpose_kernel<<<dim3(Vq/32, Dq/32, 1), tb>>>(lmw, lmwT, Dq, Vq);

    embed_kernel<<<Nrows, 128>>>(idx, tok, pos, x);

    for (int l = 0; l < Lq; l++) {
        const float* wqTl = wqT + (long)l * Hq * Dq * DHq;
        const float* wkTl = wkT + (long)l * Hq * Dq * DHq;
        const float* wvTl = wvT + (long)l * Hq * Dq * DHq;
        const float* woTl = woT + (long)l * Dq * Hq * DHq;

        // Q[h] = x @ WqT[h]^T     (M=4096, N=512, K=512, batch h)
        dim3 gq(DHq / TILE_N, Nrows / TILE_M, Hq);
        tgemm<<<gq, 256>>>(x, wqTl, nullptr, q,
            Dq, Dq, Dq, DHq,
            0L, (long)Dq * DHq, 0L, 1,
            (long)Nrows * DHq, 0L, 1, 1.0f, 0);
        tgemm<<<gq, 256>>>(x, wkTl, nullptr, k,
            Dq, Dq, Dq, DHq,
            0L, (long)Dq * DHq, 0L, 1,
            (long)Nrows * DHq, 0L, 1, 1.0f, 0);

        // Vt[h] = WvT[h] @ x^T    (M=DH=512, N=B*T=4096, K=512, batch h)
        dim3 gv(Nrows / TILE_N, DHq / TILE_M, Hq);
        tgemm<<<gv, 256>>>(wvTl, x, nullptr, vt,
            Dq, Dq, Dq, Nrows,
            (long)Dq * DHq, 0L, 0L, 1,
            (long)DHq * Nrows, 0L, 1, 1.0f, 0);

        // scores = scale * Q @ K^T  (M=N=1024, K=512, batch z=h*B+b)
        dim3 gs(Tq / TILE_N, Tq / TILE_M, Hq * Bq);
        tgemm<<<gs, 256>>>(q, k, nullptr, s,
            DHq, DHq, DHq, Tq,
            (long)Tq * DHq, (long)Tq * DHq, 0L, 1,
            (long)Tq * Tq, 0L, 1, scale, 0);

        softmax_kernel<<<Hq * Bq * Tq, 256>>>(s);

        // O = P @ Vt^T  (M=T=1024, N=DH=512, K=T=1024) -> concat [B,T,H*DH]
        dim3 gp(DHq / TILE_N, Tq / TILE_M, Hq * Bq);
        tgemm<<<gp, 256>>>(s, vt, nullptr, o,
            Tq, Tq, Nrows, Hq * DHq,
            (long)Tq * Tq, (long)DHq * Nrows, (long)Tq, Bq,
            (long)DHq, (long)Tq * Hq * DHq, Bq, 1.0f, 0);

        // attn_out = O @ WoT^T + bo
        dim3 gw(Dq / TILE_N, Nrows / TILE_M, 1);
        tgemm<<<gw, 256>>>(o, woTl, bo + (long)l * Dq, t,
            Hq * DHq, Hq * DHq, Hq * DHq, Dq,
            0L, 0L, 0L, 1, 0L, 0L, 1, 1.0f, 0);

        add_ln_kernel<<<Nrows, 128>>>(t, x, ln1g + (long)l * Dq,
                                      ln1b + (long)l * Dq, h);

        tgemm<<<gw, 256>>>(h, w1T + (long)l * Dq * Dq,
            b1 + (long)l * Dq, f,
            Dq, Dq, Dq, Dq, 0L, 0L, 0L, 1, 0L, 0L, 1, 1.0f, 1);
        tgemm<<<gw, 256>>>(f, w2T + (long)l * Dq * Dq,
            b2 + (long)l * Dq, t,
            Dq, Dq, Dq, Dq, 0L, 0L, 0L, 1, 0L, 0L, 1, 1.0f, 0);

        add_ln_kernel<<<Nrows, 128>>>(t, x, ln2g + (long)l * Dq,
                                      ln2b + (long)l * Dq, x);
    }

    // logits = x @ lmwT^T + lmb   (M=4096, N=32000, K=512)
    dim3 glm(Vq / TILE_N, Nrows / TILE_M, 1);
    tgemm<<<glm, 256>>>(x, lmwT, lmb, out,
        Dq, Dq, Dq, Vq, 0L, 0L, 0L, 1, 0L, 0L, 1, 1.0f, 0);
}

// round 7
// speedup vs baseline: 3.4368x; 1.0880x over previous
#include <cuda_runtime.h>
#include <cstdint>
#include <math.h>

#define Bq  4
#define Tq  1024
#define Dq  512
#define Hq  8
#define DHq 512
#define Lq  4
#define Vq  32000
#define Nrows (Bq*Tq)   // 4096

// ---- scratch (device globals; no allocation allowed) ----
__device__ float g_x[Nrows*Dq];
__device__ float g_h[Nrows*Dq];
__device__ float g_f[Nrows*Dq];
__device__ float g_t[Nrows*Dq];
__device__ float g_q[Hq*Nrows*DHq];              // [H,B*T,DH]
__device__ float g_k[Hq*Nrows*DHq];              // [H,B*T,DH]
__device__ float g_vt[Hq*(size_t)DHq*Nrows];     // [H,DH,B*T]  (V transposed)
__device__ float g_s[(size_t)Hq*Bq*Tq*Tq];       // [H*B,T,T]
__device__ float g_o[(size_t)Nrows*Hq*DHq];      // [B,T,H*DH]
// transposed weights (K-major NT operands everywhere)
__device__ float g_wqT[Lq*Hq*Dq*DHq];            // [L,H,DH,D]
__device__ float g_wkT[Lq*Hq*Dq*DHq];
__device__ float g_wvT[Lq*Hq*Dq*DHq];
__device__ float g_woT[Lq*Dq*Hq*DHq];            // [L,D,H*DH]
__device__ float g_w1T[Lq*Dq*Dq];
__device__ float g_w2T[Lq*Dq*Dq];
__device__ float g_lmwT[(size_t)Vq*Dq];          // [V,D]

// ===========================================================================
// TF32 helpers (sm_80-compatible path; no sm_103a-only features)
// ===========================================================================
__device__ __forceinline__ float tf32r(float x) {
    uint32_t u;
    asm("cvt.rna.tf32.f32 %0, %1;" : "=r"(u) : "f"(x));
    return __uint_as_float(u);
}
__device__ __forceinline__ void mma_tf32(float* d, const uint32_t* a,
                                         const uint32_t* b) {
    asm volatile(
        "mma.sync.aligned.m16n8k8.row.col.f32.tf32.tf32.f32 "
        "{%0,%1,%2,%3}, {%4,%5,%6,%7}, {%8,%9}, {%0,%1,%2,%3};"
        : "+f"(d[0]), "+f"(d[1]), "+f"(d[2]), "+f"(d[3])
        : "r"(a[0]), "r"(a[1]), "r"(a[2]), "r"(a[3]), "r"(b[0]), "r"(b[1]));
}

// ===========================================================================
// TF32 HMMA GEMM:  C[M,N] = alpha * A[M,K] @ B[N,K]^T (+bias) (+relu)
//   A row-major lda, B row-major ldb (K contiguous), C row-major ldc.
//   CTA tile 128 x (NIN*32); 8 warps: 2(m) x 4(n); warp tile 64 x (NIN*8).
//   K chunk 32, register-prefetch double buffer, smem double buffer.
//   batch z: A += z*sA; B += (z/inB)*sBout + (z%inB)*sBin;
//            C += (z/inC)*oCout + (z%inC)*oCin
//   M%128==0, N%(NIN*32)==0, K%32==0.
// ===========================================================================
#define TILE_M 128
#define TILE_K 32
#define KSTR   36   // padded smem row stride (floats)

template <int NIN>
__global__ __launch_bounds__(256, 1)
void tgemm(const float* __restrict__ A, const float* __restrict__ B,
           const float* __restrict__ bias, float* __restrict__ C,
           int K, int lda, int ldb, int ldc,
           long sA, long sBout, long sBin, int inB,
           long oCout, long oCin, int inC,
           float alpha, int relu) {
    constexpr int TN = NIN * 32;
    extern __shared__ float smem[];
    float* As = smem;                    // 128 * KSTR
    float* Bs = smem + TILE_M * KSTR;    // TN * KSTR

    int tid = threadIdx.x;
    int lane = tid & 31;
    int wid = tid >> 5;
    int wm = (wid & 1) * 64;           // warp m offset
    int wn = (wid >> 1) * (NIN * 8);   // warp n offset
    int g = lane >> 2, t = lane & 3;
    int z = blockIdx.z;

    const float* Ab = A + (long)blockIdx.y * TILE_M * lda + (long)z * sA;
    const float* Bb = B + (long)blockIdx.x * TN * ldb
                        + (long)(z / inB) * sBout + (long)(z % inB) * sBin;
    float* Cb = C + (long)(z / inC) * oCout + (long)(z % inC) * oCin
                  + (long)blockIdx.y * TILE_M * ldc + (long)blockIdx.x * TN;

    float acc[4][NIN][4];
#pragma unroll
    for (int i = 0; i < 4; i++)
#pragma unroll
        for (int j = 0; j < NIN; j++)
#pragma unroll
            for (int r = 0; r < 4; r++) acc[i][j][r] = 0.f;

    float4 ra[4], rb[NIN];

    // prologue load chunk 0
#pragma unroll
    for (int j = 0; j < 4; j++) {
        int idx = tid + 256 * j;
        ra[j] = *(const float4*)(Ab + (long)(idx >> 3) * lda + ((idx & 7) << 2));
    }
#pragma unroll
    for (int j = 0; j < NIN; j++) {
        int idx = tid + 256 * j;
        rb[j] = *(const float4*)(Bb + (long)(idx >> 3) * ldb + ((idx & 7) << 2));
    }

    int nch = K / TILE_K;
    for (int c = 0; c < nch; c++) {
        __syncthreads();
        // store staged chunk with tf32 rounding
#pragma unroll
        for (int j = 0; j < 4; j++) {
            int idx = tid + 256 * j;
            int off = (idx >> 3) * KSTR + ((idx & 7) << 2);
            As[off + 0] = tf32r(ra[j].x); As[off + 1] = tf32r(ra[j].y);
            As[off + 2] = tf32r(ra[j].z); As[off + 3] = tf32r(ra[j].w);
        }
#pragma unroll
        for (int j = 0; j < NIN; j++) {
            int idx = tid + 256 * j;
            int off = (idx >> 3) * KSTR + ((idx & 7) << 2);
            Bs[off + 0] = tf32r(rb[j].x); Bs[off + 1] = tf32r(rb[j].y);
            Bs[off + 2] = tf32r(rb[j].z); Bs[off + 3] = tf32r(rb[j].w);
        }
        __syncthreads();
        // prefetch next chunk into registers (overlaps compute below)
        if (c + 1 < nch) {
            int k0 = (c + 1) * TILE_K;
#pragma unroll
            for (int j = 0; j < 4; j++) {
                int idx = tid + 256 * j;
                ra[j] = *(const float4*)(Ab + (long)(idx >> 3) * lda + k0 + ((idx & 7) << 2));
            }
#pragma unroll
            for (int j = 0; j < NIN; j++) {
                int idx = tid + 256 * j;
                rb[j] = *(const float4*)(Bb + (long)(idx >> 3) * ldb + k0 + ((idx & 7) << 2));
            }
        }
        // compute current chunk: 4 k8 steps
#pragma unroll
        for (int ks = 0; ks < 4; ks++) {
            int kk = ks * 8;
            uint32_t af[4][4];
#pragma unroll
            for (int im = 0; im < 4; im++) {
                int row = wm + im * 16 + g;
                af[im][0] = __float_as_uint(As[row * KSTR + kk + t]);
                af[im][1] = __float_as_uint(As[(row + 8) * KSTR + kk + t]);
                af[im][2] = __float_as_uint(As[row * KSTR + kk + 4 + t]);
                af[im][3] = __float_as_uint(As[(row + 8) * KSTR + kk + 4 + t]);
            }
            uint32_t bf[NIN][2];
#pragma unroll
            for (int in = 0; in < NIN; in++) {
                int n = wn + in * 8 + g;
                bf[in][0] = __float_as_uint(Bs[n * KSTR + kk + t]);
                bf[in][1] = __float_as_uint(Bs[n * KSTR + kk + 4 + t]);
            }
#pragma unroll
            for (int im = 0; im < 4; im++)
#pragma unroll
                for (int in = 0; in < NIN; in++)
                    mma_tf32(acc[im][in], af[im], bf[in]);
        }
    }

    // epilogue
    int nBase = blockIdx.x * TN;
#pragma unroll
    for (int im = 0; im < 4; im++) {
#pragma unroll
        for (int in = 0; in < NIN; in++) {
            int r0 = wm + im * 16 + g;
            int cn = wn + in * 8 + t * 2;
            float2 v0, v1;
            v0.x = acc[im][in][0] * alpha;
            v0.y = acc[im][in][1] * alpha;
            v1.x = acc[im][in][2] * alpha;
            v1.y = acc[im][in][3] * alpha;
            if (bias) {
                float bx = bias[nBase + cn], by = bias[nBase + cn + 1];
                v0.x += bx; v0.y += by;
                v1.x += bx; v1.y += by;
            }
            if (relu) {
                v0.x = fmaxf(v0.x, 0.f); v0.y = fmaxf(v0.y, 0.f);
                v1.x = fmaxf(v1.x, 0.f); v1.y = fmaxf(v1.y, 0.f);
            }
            *(float2*)&Cb[(long)r0 * ldc + cn] = v0;
            *(float2*)&Cb[(long)(r0 + 8) * ldc + cn] = v1;
        }
    }
}

#define SMEM4 ((TILE_M + 128) * KSTR * 4)   // 36864
#define SMEM8 ((TILE_M + 256) * KSTR * 4)   // 55296

// ===========================================================================
// Transpose: out[z, c, r] = in[z, r, c].  R,C multiples of 32. block 32x8.
// ===========================================================================
__global__ void transpose_kernel(const float* __restrict__ in,
                                 float* __restrict__ out, int R, int C) {
    __shared__ float t[32][33];
    long zoff = (long)blockIdx.z * R * C;
    int c0 = blockIdx.x * 32, r0 = blockIdx.y * 32;
    int x = threadIdx.x, y = threadIdx.y;
#pragma unroll
    for (int j = 0; j < 32; j += 8)
        t[y + j][x] = in[zoff + (long)(r0 + y + j) * C + c0 + x];
    __syncthreads();
#pragma unroll
    for (int j = 0; j < 32; j += 8)
        out[zoff + (long)(c0 + y + j) * R + r0 + x] = t[x][y + j];
}

// ===========================================================================
// Embedding / softmax / add+LN
// ===========================================================================
__global__ void embed_kernel(const int* __restrict__ idx,
                             const float* __restrict__ tok,
                             const float* __restrict__ pos,
                             float* __restrict__ x) {
    int row = blockIdx.x;
    int t = row % Tq;
    int v = idx[row];
    const float4* te = (const float4*)(tok + (long)v * Dq);
    const float4* pe = (const float4*)(pos + (long)t * Dq);
    float4* xo = (float4*)(x + (long)row * Dq);
    for (int i = threadIdx.x; i < Dq / 4; i += blockDim.x) {
        float4 a = te[i], b = pe[i];
        xo[i] = make_float4(a.x + b.x, a.y + b.y, a.z + b.z, a.w + b.w);
    }
}

__global__ void softmax_kernel(float* __restrict__ S) {
    __shared__ float sred[8];
    float* p = S + (long)blockIdx.x * Tq;
    int tid = threadIdx.x;
    float4 v = ((const float4*)p)[tid];

    float m = fmaxf(fmaxf(v.x, v.y), fmaxf(v.z, v.w));
#pragma unroll
    for (int o = 16; o; o >>= 1) m = fmaxf(m, __shfl_xor_sync(0xffffffffu, m, o));
    if ((tid & 31) == 0) sred[tid >> 5] = m;
    __syncthreads();
    if (tid < 32) {
        float t = (tid < 8) ? sred[tid] : -1e30f;
#pragma unroll
        for (int o = 16; o; o >>= 1) t = fmaxf(t, __shfl_xor_sync(0xffffffffu, t, o));
        if (tid == 0) sred[0] = t;
    }
    __syncthreads();
    m = sred[0];
    __syncthreads();

    v.x = __expf(v.x - m); v.y = __expf(v.y - m);
    v.z = __expf(v.z - m); v.w = __expf(v.w - m);
    float s = v.x + v.y + v.z + v.w;
#pragma unroll
    for (int o = 16; o; o >>= 1) s += __shfl_xor_sync(0xffffffffu, s, o);
    if ((tid & 31) == 0) sred[tid >> 5] = s;
    __syncthreads();
    if (tid < 32) {
        float t = (tid < 8) ? sred[tid] : 0.f;
#pragma unroll
        for (int o = 16; o; o >>= 1) t += __shfl_xor_sync(0xffffffffu, t, o);
        if (tid == 0) sred[0] = t;
    }
    __syncthreads();
    float inv = 1.0f / sred[0];
    v.x *= inv; v.y *= inv; v.z *= inv; v.w *= inv;
    ((float4*)p)[tid] = v;
}

__global__ void add_ln_kernel(const float* __restrict__ a,
                              const float* __restrict__ b,
                              const float* __restrict__ g,
                              const float* __restrict__ be,
                              float* __restrict__ out) {
    __shared__ float sred[4];
    int row = blockIdx.x;
    int tid = threadIdx.x;  // 128
    float4 va = ((const float4*)(a + (long)row * Dq))[tid];
    float4 vb = ((const float4*)(b + (long)row * Dq))[tid];
    float4 v = make_float4(va.x + vb.x, va.y + vb.y, va.z + vb.z, va.w + vb.w);

    float s = v.x + v.y + v.z + v.w;
#pragma unroll
    for (int o = 16; o; o >>= 1) s += __shfl_xor_sync(0xffffffffu, s, o);
    if ((tid & 31) == 0) sred[tid >> 5] = s;
    __syncthreads();
    float mean = (sred[0] + sred[1] + sred[2] + sred[3]) * (1.0f / Dq);
    __syncthreads();

    float dx = v.x - mean, dy = v.y - mean, dz = v.z - mean, dw = v.w - mean;
    float sq = dx * dx + dy * dy + dz * dz + dw * dw;
#pragma unroll
    for (int o = 16; o; o >>= 1) sq += __shfl_xor_sync(0xffffffffu, sq, o);
    if ((tid & 31) == 0) sred[tid >> 5] = sq;
    __syncthreads();
    float var = (sred[0] + sred[1] + sred[2] + sred[3]) * (1.0f / Dq);
    float inv = rsqrtf(var + 1e-5f);

    float4 gg = ((const float4*)g)[tid];
    float4 bb = ((const float4*)be)[tid];
    float4 r;
    r.x = dx * inv * gg.x + bb.x;
    r.y = dy * inv * gg.y + bb.y;
    r.z = dz * inv * gg.z + bb.z;
    r.w = dw * inv * gg.w + bb.w;
    ((float4*)(out + (long)row * Dq))[tid] = r;
}

// ===========================================================================
extern "C" void kernel_launch(void* const* d_in, const int* in_sizes, int n_in,
                              void* d_out, int out_size) {
    const int*   idx  = (const int*)  d_in[0];
    const float* tok  = (const float*)d_in[1];
    const float* pos  = (const float*)d_in[2];
    const float* Wq   = (const float*)d_in[3];
    const float* Wk   = (const float*)d_in[4];
    const float* Wv   = (const float*)d_in[5];
    const float* Wo   = (const float*)d_in[6];
    const float* bo   = (const float*)d_in[7];
    const float* ln1g = (const float*)d_in[8];
    const float* ln1b = (const float*)d_in[9];
    const float* ln2g = (const float*)d_in[10];
    const float* ln2b = (const float*)d_in[11];
    const float* W1   = (const float*)d_in[12];
    const float* b1   = (const float*)d_in[13];
    const float* W2   = (const float*)d_in[14];
    const float* b2   = (const float*)d_in[15];
    const float* lmw  = (const float*)d_in[16];
    const float* lmb  = (const float*)d_in[17];
    float* out = (float*)d_out;

    float *x, *h, *f, *t, *q, *k, *vt, *s, *o;
    float *wqT, *wkT, *wvT, *woT, *w1T, *w2T, *lmwT;
    cudaGetSymbolAddress((void**)&x, g_x);
    cudaGetSymbolAddress((void**)&h, g_h);
    cudaGetSymbolAddress((void**)&f, g_f);
    cudaGetSymbolAddress((void**)&t, g_t);
    cudaGetSymbolAddress((void**)&q, g_q);
    cudaGetSymbolAddress((void**)&k, g_k);
    cudaGetSymbolAddress((void**)&vt, g_vt);
    cudaGetSymbolAddress((void**)&s, g_s);
    cudaGetSymbolAddress((void**)&o, g_o);
    cudaGetSymbolAddress((void**)&wqT, g_wqT);
    cudaGetSymbolAddress((void**)&wkT, g_wkT);
    cudaGetSymbolAddress((void**)&wvT, g_wvT);
    cudaGetSymbolAddress((void**)&woT, g_woT);
    cudaGetSymbolAddress((void**)&w1T, g_w1T);
    cudaGetSymbolAddress((void**)&w2T, g_w2T);
    cudaGetSymbolAddress((void**)&lmwT, g_lmwT);

    cudaFuncSetAttribute(tgemm<4>, cudaFuncAttributeMaxDynamicSharedMemorySize, SMEM4);
    cudaFuncSetAttribute(tgemm<8>, cudaFuncAttributeMaxDynamicSharedMemorySize, SMEM8);

    const float scale = 1.0f / sqrtf((float)DHq);
    dim3 tb(32, 8);

    // transpose all weights (K-major NT operands everywhere)
    transpose_kernel<<<dim3(DHq/32, Dq/32, Lq*Hq), tb>>>(Wq, wqT, Dq, DHq);
    transpose_kernel<<<dim3(DHq/32, Dq/32, Lq*Hq), tb>>>(Wk, wkT, Dq, DHq);
    transpose_kernel<<<dim3(DHq/32, Dq/32, Lq*Hq), tb>>>(Wv, wvT, Dq, DHq);
    transpose_kernel<<<dim3(Dq/32, (Hq*DHq)/32, Lq), tb>>>(Wo, woT, Hq*DHq, Dq);
    transpose_kernel<<<dim3(Dq/32, Dq/32, Lq), tb>>>(W1, w1T, Dq, Dq);
    transpose_kernel<<<dim3(Dq/32, Dq/32, Lq), tb>>>(W2, w2T, Dq, Dq);
    transpose_kernel<<<dim3(Vq/32, Dq/32, 1), tb>>>(lmw, lmwT, Dq, Vq);

    embed_kernel<<<Nrows, 128>>>(idx, tok, pos, x);

    for (int l = 0; l < Lq; l++) {
        const float* wqTl = wqT + (long)l * Hq * Dq * DHq;
        const float* wkTl = wkT + (long)l * Hq * Dq * DHq;
        const float* wvTl = wvT + (long)l * Hq * Dq * DHq;
        const float* woTl = woT + (long)l * Dq * Hq * DHq;

        // Q[h] = x @ WqT[h]^T     (M=4096, N=512, K=512, batch h)
        dim3 gq(DHq / 256, Nrows / TILE_M, Hq);
        tgemm<8><<<gq, 256, SMEM8>>>(x, wqTl, nullptr, q,
            Dq, Dq, Dq, DHq,
            0L, (long)Dq * DHq, 0L, 1,
            (long)Nrows * DHq, 0L, 1, 1.0f, 0);
        tgemm<8><<<gq, 256, SMEM8>>>(x, wkTl, nullptr, k,
            Dq, Dq, Dq, DHq,
            0L, (long)Dq * DHq, 0L, 1,
            (long)Nrows * DHq, 0L, 1, 1.0f, 0);

        // Vt[h] = WvT[h] @ x^T    (M=DH=512, N=B*T=4096, K=512, batch h)
        dim3 gv(Nrows / 256, DHq / TILE_M, Hq);
        tgemm<8><<<gv, 256, SMEM8>>>(wvTl, x, nullptr, vt,
            Dq, Dq, Dq, Nrows,
            (long)Dq * DHq, 0L, 0L, 1,
            (long)DHq * Nrows, 0L, 1, 1.0f, 0);

        // scores = scale * Q @ K^T  (M=N=1024, K=512, batch z=h*B+b)
        dim3 gs(Tq / 256, Tq / TILE_M, Hq * Bq);
        tgemm<8><<<gs, 256, SMEM8>>>(q, k, nullptr, s,
            DHq, DHq, DHq, Tq,
            (long)Tq * DHq, (long)Tq * DHq, 0L, 1,
            (long)Tq * Tq, 0L, 1, scale, 0);

        softmax_kernel<<<Hq * Bq * Tq, 256>>>(s);

        // O = P @ Vt^T  (M=T=1024, N=DH=512, K=T=1024) -> concat [B,T,H*DH]
        dim3 gp(DHq / 256, Tq / TILE_M, Hq * Bq);
        tgemm<8><<<gp, 256, SMEM8>>>(s, vt, nullptr, o,
            Tq, Tq, Nrows, Hq * DHq,
            (long)Tq * Tq, (long)DHq * Nrows, (long)Tq, Bq,
            (long)DHq, (long)Tq * Hq * DHq, Bq, 1.0f, 0);

        // attn_out = O @ WoT^T + bo   (narrow N, unbatched -> 128-wide tile)
        dim3 gw(Dq / 128, Nrows / TILE_M, 1);
        tgemm<4><<<gw, 256, SMEM4>>>(o, woTl, bo + (long)l * Dq, t,
            Hq * DHq, Hq * DHq, Hq * DHq, Dq,
            0L, 0L, 0L, 1, 0L, 0L, 1, 1.0f, 0);

        add_ln_kernel<<<Nrows, 128>>>(t, x, ln1g + (long)l * Dq,
                                      ln1b + (long)l * Dq, h);

        tgemm<4><<<gw, 256, SMEM4>>>(h, w1T + (long)l * Dq * Dq,
            b1 + (long)l * Dq, f,
            Dq, Dq, Dq, Dq, 0L, 0L, 0L, 1, 0L, 0L, 1, 1.0f, 1);
        tgemm<4><<<gw, 256, SMEM4>>>(f, w2T + (long)l * Dq * Dq,
            b2 + (long)l * Dq, t,
            Dq, Dq, Dq, Dq, 0L, 0L, 0L, 1, 0L, 0L, 1, 1.0f, 0);

        add_ln_kernel<<<Nrows, 128>>>(t, x, ln2g + (long)l * Dq,
                                      ln2b + (long)l * Dq, x);
    }

    // logits = x @ lmwT^T + lmb   (M=4096, N=32000, K=512)
    dim3 glm(Vq / 256, Nrows / TILE_M, 1);
    tgemm<8><<<glm, 256, SMEM8>>>(x, lmwT, lmb, out,
        Dq, Dq, Dq, Vq, 0L, 0L, 0L, 1, 0L, 0L, 1, 1.0f, 0);
}

// round 8
// speedup vs baseline: 3.6709x; 1.0681x over previous
#include <cuda_runtime.h>
#include <cstdint>
#include <math.h>

#define Bq  4
#define Tq  1024
#define Dq  512
#define Hq  8
#define DHq 512
#define Lq  4
#define Vq  32000
#define Nrows (Bq*Tq)   // 4096

// ---- scratch (device globals; no allocation allowed) ----
__device__ float g_x[Nrows*Dq];                  // residual (full precision)
__device__ float g_xr[Nrows*Dq];                 // residual, tf32-rounded copy
__device__ float g_h[Nrows*Dq];                  // post-LN1 (tf32-rounded)
__device__ float g_f[Nrows*Dq];                  // ffn hidden (tf32-rounded)
__device__ float g_t[Nrows*Dq];                  // attn_out / ffn out (full)
__device__ float g_q[Hq*Nrows*DHq];              // [H,B*T,DH] (rounded)
__device__ float g_k[Hq*Nrows*DHq];              // [H,B*T,DH] (rounded)
__device__ float g_vt[Hq*(size_t)DHq*Nrows];     // [H,DH,B*T] (rounded)
__device__ float g_s[(size_t)Hq*Bq*Tq*Tq];       // [H*B,T,T] scores/probs
__device__ float g_o[(size_t)Nrows*Hq*DHq];      // [B,T,H*DH] (rounded)
// transposed weights, tf32-rounded (K-major NT operands everywhere)
__device__ float g_wqT[Lq*Hq*Dq*DHq];            // [L,H,DH,D]
__device__ float g_wkT[Lq*Hq*Dq*DHq];
__device__ float g_wvT[Lq*Hq*Dq*DHq];
__device__ float g_woT[Lq*Dq*Hq*DHq];            // [L,D,H*DH]
__device__ float g_w1T[Lq*Dq*Dq];
__device__ float g_w2T[Lq*Dq*Dq];
__device__ float g_lmwT[(size_t)Vq*Dq];          // [V,D]

// ===========================================================================
// helpers
// ===========================================================================
__device__ __forceinline__ float tf32r(float x) {
    uint32_t u;
    asm("cvt.rna.tf32.f32 %0, %1;" : "=r"(u) : "f"(x));
    return __uint_as_float(u);
}
__device__ __forceinline__ void mma_tf32(float* d, const uint32_t* a,
                                         const uint32_t* b) {
    asm volatile(
        "mma.sync.aligned.m16n8k8.row.col.f32.tf32.tf32.f32 "
        "{%0,%1,%2,%3}, {%4,%5,%6,%7}, {%8,%9}, {%0,%1,%2,%3};"
        : "+f"(d[0]), "+f"(d[1]), "+f"(d[2]), "+f"(d[3])
        : "r"(a[0]), "r"(a[1]), "r"(a[2]), "r"(a[3]), "r"(b[0]), "r"(b[1]));
}
__device__ __forceinline__ uint32_t smem_u32(const void* p) {
    uint32_t a;
    asm("{ .reg .u64 t; cvta.to.shared.u64 t, %1; cvt.u32.u64 %0, t; }"
        : "=r"(a) : "l"(p));
    return a;
}
#define CP_ASYNC16(dst, src) \
    asm volatile("cp.async.cg.shared.global [%0], [%1], 16;" \
                 :: "r"(dst), "l"(src))
#define CP_COMMIT() asm volatile("cp.async.commit_group;" ::: "memory")
#define CP_WAIT1()  asm volatile("cp.async.wait_group 1;" ::: "memory")

// ===========================================================================
// TF32 HMMA GEMM (inputs MUST already be tf32-rounded fp32):
//   C[M,N] = alpha * A[M,K] @ B[N,K]^T (+bias) (+relu) (+tf32 round of output)
//   CTA tile 128 x (NIN*32); 8 warps: 2(m) x 4(n); warp tile 64 x (NIN*8).
//   K chunk 32; cp.async 3-stage pipeline.
//   batch z: A += z*sA; B += (z/inB)*sBout + (z%inB)*sBin;
//            C += (z/inC)*oCout + (z%inC)*oCin
//   M%128==0, N%(NIN*32)==0, K%32==0, K>=96.
// ===========================================================================
#define TILE_M 128
#define TILE_K 32
#define KSTR   36   // padded smem row stride (floats) -> conflict-free LDS
#define STAGES 3

template <int NIN>
__device__ __forceinline__ void issue_chunk(const float* __restrict__ Ab,
                                            const float* __restrict__ Bb,
                                            int lda, int ldb, int k0,
                                            uint32_t stA, uint32_t stB, int tid) {
#pragma unroll
    for (int j = 0; j < 4; j++) {
        int idx = tid + 256 * j;
        int row = idx >> 3, col = (idx & 7) << 2;
        uint32_t dst = stA + (uint32_t)(row * KSTR + col) * 4u;
        CP_ASYNC16(dst, Ab + (long)row * lda + k0 + col);
    }
#pragma unroll
    for (int j = 0; j < NIN; j++) {
        int idx = tid + 256 * j;
        int row = idx >> 3, col = (idx & 7) << 2;
        uint32_t dst = stB + (uint32_t)(row * KSTR + col) * 4u;
        CP_ASYNC16(dst, Bb + (long)row * ldb + k0 + col);
    }
    CP_COMMIT();
}

template <int NIN>
__global__ __launch_bounds__(256, 1)
void tgemm(const float* __restrict__ A, const float* __restrict__ B,
           const float* __restrict__ bias, float* __restrict__ C,
           int K, int lda, int ldb, int ldc,
           long sA, long sBout, long sBin, int inB,
           long oCout, long oCin, int inC,
           float alpha, int relu, int rnd) {
    constexpr int TN = NIN * 32;
    constexpr int STG_FLOATS = (TILE_M + TN) * KSTR;
    extern __shared__ __align__(16) float smem[];
    uint32_t smemBase = smem_u32(smem);
    const uint32_t STG_BYTES = STG_FLOATS * 4;
    const uint32_t AB_OFF = TILE_M * KSTR * 4;

    int tid = threadIdx.x;
    int lane = tid & 31;
    int wid = tid >> 5;
    int wm = (wid & 1) * 64;           // warp m offset
    int wn = (wid >> 1) * (NIN * 8);   // warp n offset
    int g = lane >> 2, t = lane & 3;
    int z = blockIdx.z;

    const float* Ab = A + (long)blockIdx.y * TILE_M * lda + (long)z * sA;
    const float* Bb = B + (long)blockIdx.x * TN * ldb
                        + (long)(z / inB) * sBout + (long)(z % inB) * sBin;
    float* Cb = C + (long)(z / inC) * oCout + (long)(z % inC) * oCin
                  + (long)blockIdx.y * TILE_M * ldc + (long)blockIdx.x * TN;

    float acc[4][NIN][4];
#pragma unroll
    for (int i = 0; i < 4; i++)
#pragma unroll
        for (int j = 0; j < NIN; j++)
#pragma unroll
            for (int r = 0; r < 4; r++) acc[i][j][r] = 0.f;

    int nch = K / TILE_K;
    // prologue: stages 0,1
    issue_chunk<NIN>(Ab, Bb, lda, ldb, 0, smemBase, smemBase + AB_OFF, tid);
    issue_chunk<NIN>(Ab, Bb, lda, ldb, TILE_K,
                     smemBase + STG_BYTES, smemBase + STG_BYTES + AB_OFF, tid);

    int stC = 0;   // compute stage for chunk c
    int stI = 2;   // issue stage for chunk c+2
    for (int c = 0; c < nch; c++) {
        CP_WAIT1();            // chunk c resident
        __syncthreads();       // visible to all warps; prior reads of stI done
        if (c + 2 < nch) {
            uint32_t sb = smemBase + (uint32_t)stI * STG_BYTES;
            issue_chunk<NIN>(Ab, Bb, lda, ldb, (c + 2) * TILE_K,
                             sb, sb + AB_OFF, tid);
        }
        const float* As = smem + stC * STG_FLOATS;
        const float* Bs = As + TILE_M * KSTR;
#pragma unroll
        for (int ks = 0; ks < 4; ks++) {
            int kk = ks * 8;
            uint32_t af[4][4];
#pragma unroll
            for (int im = 0; im < 4; im++) {
                int row = wm + im * 16 + g;
                af[im][0] = __float_as_uint(As[row * KSTR + kk + t]);
                af[im][1] = __float_as_uint(As[(row + 8) * KSTR + kk + t]);
                af[im][2] = __float_as_uint(As[row * KSTR + kk + 4 + t]);
                af[im][3] = __float_as_uint(As[(row + 8) * KSTR + kk + 4 + t]);
            }
            uint32_t bf[NIN][2];
#pragma unroll
            for (int in = 0; in < NIN; in++) {
                int n = wn + in * 8 + g;
                bf[in][0] = __float_as_uint(Bs[n * KSTR + kk + t]);
                bf[in][1] = __float_as_uint(Bs[n * KSTR + kk + 4 + t]);
            }
#pragma unroll
            for (int im = 0; im < 4; im++)
#pragma unroll
                for (int in = 0; in < NIN; in++)
                    mma_tf32(acc[im][in], af[im], bf[in]);
        }
        stC++; if (stC == STAGES) stC = 0;
        stI++; if (stI == STAGES) stI = 0;
    }

    // epilogue
    int nBase = blockIdx.x * TN;
#pragma unroll
    for (int im = 0; im < 4; im++) {
#pragma unroll
        for (int in = 0; in < NIN; in++) {
            int r0 = wm + im * 16 + g;
            int cn = wn + in * 8 + t * 2;
            float2 v0, v1;
            v0.x = acc[im][in][0] * alpha;
            v0.y = acc[im][in][1] * alpha;
            v1.x = acc[im][in][2] * alpha;
            v1.y = acc[im][in][3] * alpha;
            if (bias) {
                float bx = bias[nBase + cn], by = bias[nBase + cn + 1];
                v0.x += bx; v0.y += by;
                v1.x += bx; v1.y += by;
            }
            if (relu) {
                v0.x = fmaxf(v0.x, 0.f); v0.y = fmaxf(v0.y, 0.f);
                v1.x = fmaxf(v1.x, 0.f); v1.y = fmaxf(v1.y, 0.f);
            }
            if (rnd) {
                v0.x = tf32r(v0.x); v0.y = tf32r(v0.y);
                v1.x = tf32r(v1.x); v1.y = tf32r(v1.y);
            }
            *(float2*)&Cb[(long)r0 * ldc + cn] = v0;
            *(float2*)&Cb[(long)(r0 + 8) * ldc + cn] = v1;
        }
    }
}

#define SMEM4 (STAGES * (TILE_M + 128) * KSTR * 4)   // 110592
#define SMEM8 (STAGES * (TILE_M + 256) * KSTR * 4)   // 165888

// ===========================================================================
// Transpose + tf32 round: out[z, c, r] = tf32(in[z, r, c]).
// ===========================================================================
__global__ void transpose_kernel(const float* __restrict__ in,
                                 float* __restrict__ out, int R, int C) {
    __shared__ float t[32][33];
    long zoff = (long)blockIdx.z * R * C;
    int c0 = blockIdx.x * 32, r0 = blockIdx.y * 32;
    int x = threadIdx.x, y = threadIdx.y;
#pragma unroll
    for (int j = 0; j < 32; j += 8)
        t[y + j][x] = in[zoff + (long)(r0 + y + j) * C + c0 + x];
    __syncthreads();
#pragma unroll
    for (int j = 0; j < 32; j += 8)
        out[zoff + (long)(c0 + y + j) * R + r0 + x] = tf32r(t[x][y + j]);
}

// ===========================================================================
// Embedding: x full + xr (tf32-rounded copy)
// ===========================================================================
__global__ void embed_kernel(const int* __restrict__ idx,
                             const float* __restrict__ tok,
                             const float* __restrict__ pos,
                             float* __restrict__ x,
                             float* __restrict__ xr) {
    int row = blockIdx.x;
    int t = row % Tq;
    int v = idx[row];
    const float4* te = (const float4*)(tok + (long)v * Dq);
    const float4* pe = (const float4*)(pos + (long)t * Dq);
    float4* xo = (float4*)(x + (long)row * Dq);
    float4* xro = (float4*)(xr + (long)row * Dq);
    for (int i = threadIdx.x; i < Dq / 4; i += blockDim.x) {
        float4 a = te[i], b = pe[i];
        float4 v4 = make_float4(a.x + b.x, a.y + b.y, a.z + b.z, a.w + b.w);
        xo[i] = v4;
        xro[i] = make_float4(tf32r(v4.x), tf32r(v4.y), tf32r(v4.z), tf32r(v4.w));
    }
}

// ===========================================================================
// Row softmax over 1024 cols, in place, output tf32-rounded (feeds PV GEMM).
// ===========================================================================
__global__ void softmax_kernel(float* __restrict__ S) {
    __shared__ float sred[8];
    float* p = S + (long)blockIdx.x * Tq;
    int tid = threadIdx.x;
    float4 v = ((const float4*)p)[tid];

    float m = fmaxf(fmaxf(v.x, v.y), fmaxf(v.z, v.w));
#pragma unroll
    for (int o = 16; o; o >>= 1) m = fmaxf(m, __shfl_xor_sync(0xffffffffu, m, o));
    if ((tid & 31) == 0) sred[tid >> 5] = m;
    __syncthreads();
    if (tid < 32) {
        float t = (tid < 8) ? sred[tid] : -1e30f;
#pragma unroll
        for (int o = 16; o; o >>= 1) t = fmaxf(t, __shfl_xor_sync(0xffffffffu, t, o));
        if (tid == 0) sred[0] = t;
    }
    __syncthreads();
    m = sred[0];
    __syncthreads();

    v.x = __expf(v.x - m); v.y = __expf(v.y - m);
    v.z = __expf(v.z - m); v.w = __expf(v.w - m);
    float s = v.x + v.y + v.z + v.w;
#pragma unroll
    for (int o = 16; o; o >>= 1) s += __shfl_xor_sync(0xffffffffu, s, o);
    if ((tid & 31) == 0) sred[tid >> 5] = s;
    __syncthreads();
    if (tid < 32) {
        float t = (tid < 8) ? sred[tid] : 0.f;
#pragma unroll
        for (int o = 16; o; o >>= 1) t += __shfl_xor_sync(0xffffffffu, t, o);
        if (tid == 0) sred[0] = t;
    }
    __syncthreads();
    float inv = 1.0f / sred[0];
    v.x = tf32r(v.x * inv); v.y = tf32r(v.y * inv);
    v.z = tf32r(v.z * inv); v.w = tf32r(v.w * inv);
    ((float4*)p)[tid] = v;
}

// ===========================================================================
// out = LayerNorm(a + b) * g + be.
//   roundMain: round the primary output to tf32 (when it feeds only GEMMs)
//   outR (optional): additional tf32-rounded copy (residual + GEMM input)
// ===========================================================================
__global__ void add_ln_kernel(const float* __restrict__ a,
                              const float* __restrict__ b,
                              const float* __restrict__ g,
                              const float* __restrict__ be,
                              float* __restrict__ out,
                              float* __restrict__ outR,
                              int roundMain) {
    __shared__ float sred[4];
    int row = blockIdx.x;
    int tid = threadIdx.x;  // 128
    float4 va = ((const float4*)(a + (long)row * Dq))[tid];
    float4 vb = ((const float4*)(b + (long)row * Dq))[tid];
    float4 v = make_float4(va.x + vb.x, va.y + vb.y, va.z + vb.z, va.w + vb.w);

    float s = v.x + v.y + v.z + v.w;
#pragma unroll
    for (int o = 16; o; o >>= 1) s += __shfl_xor_sync(0xffffffffu, s, o);
    if ((tid & 31) == 0) sred[tid >> 5] = s;
    __syncthreads();
    float mean = (sred[0] + sred[1] + sred[2] + sred[3]) * (1.0f / Dq);
    __syncthreads();

    float dx = v.x - mean, dy = v.y - mean, dz = v.z - mean, dw = v.w - mean;
    float sq = dx * dx + dy * dy + dz * dz + dw * dw;
#pragma unroll
    for (int o = 16; o; o >>= 1) sq += __shfl_xor_sync(0xffffffffu, sq, o);
    if ((tid & 31) == 0) sred[tid >> 5] = sq;
    __syncthreads();
    float var = (sred[0] + sred[1] + sred[2] + sred[3]) * (1.0f / Dq);
    float inv = rsqrtf(var + 1e-5f);

    float4 gg = ((const float4*)g)[tid];
    float4 bb = ((const float4*)be)[tid];
    float4 r;
    r.x = dx * inv * gg.x + bb.x;
    r.y = dy * inv * gg.y + bb.y;
    r.z = dz * inv * gg.z + bb.z;
    r.w = dw * inv * gg.w + bb.w;
    if (roundMain) {
        r.x = tf32r(r.x); r.y = tf32r(r.y);
        r.z = tf32r(r.z); r.w = tf32r(r.w);
    }
    ((float4*)(out + (long)row * Dq))[tid] = r;
    if (outR) {
        float4 rr = make_float4(tf32r(r.x), tf32r(r.y), tf32r(r.z), tf32r(r.w));
        ((float4*)(outR + (long)row * Dq))[tid] = rr;
    }
}

// ===========================================================================
extern "C" void kernel_launch(void* const* d_in, const int* in_sizes, int n_in,
                              void* d_out, int out_size) {
    const int*   idx  = (const int*)  d_in[0];
    const float* tok  = (const float*)d_in[1];
    const float* pos  = (const float*)d_in[2];
    const float* Wq   = (const float*)d_in[3];
    const float* Wk   = (const float*)d_in[4];
    const float* Wv   = (const float*)d_in[5];
    const float* Wo   = (const float*)d_in[6];
    const float* bo   = (const float*)d_in[7];
    const float* ln1g = (const float*)d_in[8];
    const float* ln1b = (const float*)d_in[9];
    const float* ln2g = (const float*)d_in[10];
    const float* ln2b = (const float*)d_in[11];
    const float* W1   = (const float*)d_in[12];
    const float* b1   = (const float*)d_in[13];
    const float* W2   = (const float*)d_in[14];
    const float* b2   = (const float*)d_in[15];
    const float* lmw  = (const float*)d_in[16];
    const float* lmb  = (const float*)d_in[17];
    float* out = (float*)d_out;

    float *x, *xr, *h, *f, *t, *q, *k, *vt, *s, *o;
    float *wqT, *wkT, *wvT, *woT, *w1T, *w2T, *lmwT;
    cudaGetSymbolAddress((void**)&x, g_x);
    cudaGetSymbolAddress((void**)&xr, g_xr);
    cudaGetSymbolAddress((void**)&h, g_h);
    cudaGetSymbolAddress((void**)&f, g_f);
    cudaGetSymbolAddress((void**)&t, g_t);
    cudaGetSymbolAddress((void**)&q, g_q);
    cudaGetSymbolAddress((void**)&k, g_k);
    cudaGetSymbolAddress((void**)&vt, g_vt);
    cudaGetSymbolAddress((void**)&s, g_s);
    cudaGetSymbolAddress((void**)&o, g_o);
    cudaGetSymbolAddress((void**)&wqT, g_wqT);
    cudaGetSymbolAddress((void**)&wkT, g_wkT);
    cudaGetSymbolAddress((void**)&wvT, g_wvT);
    cudaGetSymbolAddress((void**)&woT, g_woT);
    cudaGetSymbolAddress((void**)&w1T, g_w1T);
    cudaGetSymbolAddress((void**)&w2T, g_w2T);
    cudaGetSymbolAddress((void**)&lmwT, g_lmwT);

    cudaFuncSetAttribute(tgemm<4>, cudaFuncAttributeMaxDynamicSharedMemorySize, SMEM4);
    cudaFuncSetAttribute(tgemm<8>, cudaFuncAttributeMaxDynamicSharedMemorySize, SMEM8);

    const float scale = 1.0f / sqrtf((float)DHq);
    dim3 tb(32, 8);

    // transpose + round all weights (K-major NT operands everywhere)
    transpose_kernel<<<dim3(DHq/32, Dq/32, Lq*Hq), tb>>>(Wq, wqT, Dq, DHq);
    transpose_kernel<<<dim3(DHq/32, Dq/32, Lq*Hq), tb>>>(Wk, wkT, Dq, DHq);
    transpose_kernel<<<dim3(DHq/32, Dq/32, Lq*Hq), tb>>>(Wv, wvT, Dq, DHq);
    transpose_kernel<<<dim3(Dq/32, (Hq*DHq)/32, Lq), tb>>>(Wo, woT, Hq*DHq, Dq);
    transpose_kernel<<<dim3(Dq/32, Dq/32, Lq), tb>>>(W1, w1T, Dq, Dq);
    transpose_kernel<<<dim3(Dq/32, Dq/32, Lq), tb>>>(W2, w2T, Dq, Dq);
    transpose_kernel<<<dim3(Vq/32, Dq/32, 1), tb>>>(lmw, lmwT, Dq, Vq);

    embed_kernel<<<Nrows, 128>>>(idx, tok, pos, x, xr);

    for (int l = 0; l < Lq; l++) {
        const float* wqTl = wqT + (long)l * Hq * Dq * DHq;
        const float* wkTl = wkT + (long)l * Hq * Dq * DHq;
        const float* wvTl = wvT + (long)l * Hq * Dq * DHq;
        const float* woTl = woT + (long)l * Dq * Hq * DHq;

        // Q[h] = xr @ WqT[h]^T     (M=4096, N=512, K=512, batch h) -> rounded
        dim3 gq(DHq / 256, Nrows / TILE_M, Hq);
        tgemm<8><<<gq, 256, SMEM8>>>(xr, wqTl, nullptr, q,
            Dq, Dq, Dq, DHq,
            0L, (long)Dq * DHq, 0L, 1,
            (long)Nrows * DHq, 0L, 1, 1.0f, 0, 1);
        tgemm<8><<<gq, 256, SMEM8>>>(xr, wkTl, nullptr, k,
            Dq, Dq, Dq, DHq,
            0L, (long)Dq * DHq, 0L, 1,
            (long)Nrows * DHq, 0L, 1, 1.0f, 0, 1);

        // Vt[h] = WvT[h] @ xr^T    (M=DH=512, N=B*T=4096, K=512) -> rounded
        dim3 gv(Nrows / 256, DHq / TILE_M, Hq);
        tgemm<8><<<gv, 256, SMEM8>>>(wvTl, xr, nullptr, vt,
            Dq, Dq, Dq, Nrows,
            (long)Dq * DHq, 0L, 0L, 1,
            (long)DHq * Nrows, 0L, 1, 1.0f, 0, 1);

        // scores = scale * Q @ K^T  (M=N=1024, K=512, batch z=h*B+b)
        dim3 gs(Tq / 256, Tq / TILE_M, Hq * Bq);
        tgemm<8><<<gs, 256, SMEM8>>>(q, k, nullptr, s,
            DHq, DHq, DHq, Tq,
            (long)Tq * DHq, (long)Tq * DHq, 0L, 1,
            (long)Tq * Tq, 0L, 1, scale, 0, 0);

        softmax_kernel<<<Hq * Bq * Tq, 256>>>(s);

        // O = P @ Vt^T  (M=T=1024, N=DH=512, K=T=1024) -> concat, rounded
        dim3 gp(DHq / 256, Tq / TILE_M, Hq * Bq);
        tgemm<8><<<gp, 256, SMEM8>>>(s, vt, nullptr, o,
            Tq, Tq, Nrows, Hq * DHq,
            (long)Tq * Tq, (long)DHq * Nrows, (long)Tq, Bq,
            (long)DHq, (long)Tq * Hq * DHq, Bq, 1.0f, 0, 1);

        // attn_out = O @ WoT^T + bo   (narrow N, unbatched -> 128-wide tile)
        dim3 gw(Dq / 128, Nrows / TILE_M, 1);
        tgemm<4><<<gw, 256, SMEM4>>>(o, woTl, bo + (long)l * Dq, t,
            Hq * DHq, Hq * DHq, Hq * DHq, Dq,
            0L, 0L, 0L, 1, 0L, 0L, 1, 1.0f, 0, 0);

        // h = LN(attn_out + x), rounded (feeds only W1 GEMM)
        add_ln_kernel<<<Nrows, 128>>>(t, x, ln1g + (long)l * Dq,
                                      ln1b + (long)l * Dq, h, nullptr, 1);

        tgemm<4><<<gw, 256, SMEM4>>>(h, w1T + (long)l * Dq * Dq,
            b1 + (long)l * Dq, f,
            Dq, Dq, Dq, Dq, 0L, 0L, 0L, 1, 0L, 0L, 1, 1.0f, 1, 1);
        tgemm<4><<<gw, 256, SMEM4>>>(f, w2T + (long)l * Dq * Dq,
            b2 + (long)l * Dq, t,
            Dq, Dq, Dq, Dq, 0L, 0L, 0L, 1, 0L, 0L, 1, 1.0f, 0, 0);

        // x = LN(ff + x) full + rounded copy xr
        add_ln_kernel<<<Nrows, 128>>>(t, x, ln2g + (long)l * Dq,
                                      ln2b + (long)l * Dq, x, xr, 0);
    }

    // logits = xr @ lmwT^T + lmb   (M=4096, N=32000, K=512)
    dim3 glm(Vq / 256, Nrows / TILE_M, 1);
    tgemm<8><<<glm, 256, SMEM8>>>(xr, lmwT, lmb, out,
        Dq, Dq, Dq, Vq, 0L, 0L, 0L, 1, 0L, 0L, 1, 1.0f, 0, 0);
}

// round 9
// speedup vs baseline: 3.6751x; 1.0011x over previous
#include <cuda_runtime.h>
#include <cstdint>
#include <math.h>

#define Bq  4
#define Tq  1024
#define Dq  512
#define Hq  8
#define DHq 512
#define Lq  4
#define Vq  32000
#define Nrows (Bq*Tq)   // 4096

// ---- scratch (device globals; no allocation allowed) ----
__device__ float g_x[Nrows*Dq];                  // residual (full precision)
__device__ float g_xr[Nrows*Dq];                 // residual, tf32-rounded copy
__device__ float g_h[Nrows*Dq];                  // post-LN1 (tf32-rounded)
__device__ float g_f[Nrows*Dq];                  // ffn hidden (tf32-rounded)
__device__ float g_t[Nrows*Dq];                  // attn_out / ffn out (full)
__device__ float g_q[Hq*Nrows*DHq];              // [H,B*T,DH] (rounded)
__device__ float g_k[Hq*Nrows*DHq];              // [H,B*T,DH] (rounded)
__device__ float g_vt[Hq*(size_t)DHq*Nrows];     // [H,DH,B*T] (rounded)
__device__ float g_s[(size_t)Hq*Bq*Tq*Tq];       // [H*B,T,T] scores/probs
__device__ float g_o[(size_t)Nrows*Hq*DHq];      // [B,T,H*DH] (rounded)
// transposed weights, tf32-rounded (K-major NT operands everywhere)
__device__ float g_wqT[Lq*Hq*Dq*DHq];            // [L,H,DH,D]
__device__ float g_wkT[Lq*Hq*Dq*DHq];
__device__ float g_wvT[Lq*Hq*Dq*DHq];
__device__ float g_woT[Lq*Dq*Hq*DHq];            // [L,D,H*DH]
__device__ float g_w1T[Lq*Dq*Dq];
__device__ float g_w2T[Lq*Dq*Dq];
__device__ float g_lmwT[(size_t)Vq*Dq];          // [V,D]

// ===========================================================================
// helpers
// ===========================================================================
__device__ __forceinline__ float tf32r(float x) {
    uint32_t u;
    asm("cvt.rna.tf32.f32 %0, %1;" : "=r"(u) : "f"(x));
    return __uint_as_float(u);
}
__device__ __forceinline__ void mma_tf32(float* d, const uint32_t* a,
                                         const uint32_t* b) {
    asm volatile(
        "mma.sync.aligned.m16n8k8.row.col.f32.tf32.tf32.f32 "
        "{%0,%1,%2,%3}, {%4,%5,%6,%7}, {%8,%9}, {%0,%1,%2,%3};"
        : "+f"(d[0]), "+f"(d[1]), "+f"(d[2]), "+f"(d[3])
        : "r"(a[0]), "r"(a[1]), "r"(a[2]), "r"(a[3]), "r"(b[0]), "r"(b[1]));
}
__device__ __forceinline__ uint32_t smem_u32(const void* p) {
    uint32_t a;
    asm("{ .reg .u64 t; cvta.to.shared.u64 t, %1; cvt.u32.u64 %0, t; }"
        : "=r"(a) : "l"(p));
    return a;
}
#define CP_ASYNC16(dst, src) \
    asm volatile("cp.async.cg.shared.global [%0], [%1], 16;" \
                 :: "r"(dst), "l"(src))
#define CP_COMMIT() asm volatile("cp.async.commit_group;" ::: "memory")
#define CP_WAIT1()  asm volatile("cp.async.wait_group 1;" ::: "memory")

// ===========================================================================
// TF32 HMMA GEMM (inputs MUST already be tf32-rounded fp32):
//   C[M,N] = alpha * A[M,K] @ B[N,K]^T (+bias) (+relu) (+tf32 round of output)
//   CTA tile 128 x (NIN*32); 8 warps: 2(m) x 4(n); warp tile 64 x (NIN*8).
//   K chunk 32; cp.async 3-stage smem pipeline; double-buffered fragments.
//   batch z: A += z*sA; B += (z/inB)*sBout + (z%inB)*sBin;
//            C += (z/inC)*oCout + (z%inC)*oCin
//   M%128==0, N%(NIN*32)==0, K%32==0, K>=96.
// ===========================================================================
#define TILE_M 128
#define TILE_K 32
#define KSTR   36   // padded smem row stride (floats) -> conflict-free LDS
#define STAGES 3

template <int NIN>
__device__ __forceinline__ void issue_chunk(const float* __restrict__ Ab,
                                            const float* __restrict__ Bb,
                                            int lda, int ldb, int k0,
                                            uint32_t stA, uint32_t stB, int tid) {
#pragma unroll
    for (int j = 0; j < 4; j++) {
        int idx = tid + 256 * j;
        int row = idx >> 3, col = (idx & 7) << 2;
        uint32_t dst = stA + (uint32_t)(row * KSTR + col) * 4u;
        CP_ASYNC16(dst, Ab + (long)row * lda + k0 + col);
    }
#pragma unroll
    for (int j = 0; j < NIN; j++) {
        int idx = tid + 256 * j;
        int row = idx >> 3, col = (idx & 7) << 2;
        uint32_t dst = stB + (uint32_t)(row * KSTR + col) * 4u;
        CP_ASYNC16(dst, Bb + (long)row * ldb + k0 + col);
    }
    CP_COMMIT();
}

template <int NIN>
__device__ __forceinline__ void load_frags(const float* __restrict__ As,
                                           const float* __restrict__ Bs,
                                           int kk, int wm, int wn, int g, int t,
                                           uint32_t af[4][4], uint32_t bf[][2]) {
#pragma unroll
    for (int im = 0; im < 4; im++) {
        int row = wm + im * 16 + g;
        af[im][0] = __float_as_uint(As[row * KSTR + kk + t]);
        af[im][1] = __float_as_uint(As[(row + 8) * KSTR + kk + t]);
        af[im][2] = __float_as_uint(As[row * KSTR + kk + 4 + t]);
        af[im][3] = __float_as_uint(As[(row + 8) * KSTR + kk + 4 + t]);
    }
#pragma unroll
    for (int in = 0; in < NIN; in++) {
        int n = wn + in * 8 + g;
        bf[in][0] = __float_as_uint(Bs[n * KSTR + kk + t]);
        bf[in][1] = __float_as_uint(Bs[n * KSTR + kk + 4 + t]);
    }
}

template <int NIN>
__global__ __launch_bounds__(256, 1)
void tgemm(const float* __restrict__ A, const float* __restrict__ B,
           const float* __restrict__ bias, float* __restrict__ C,
           int K, int lda, int ldb, int ldc,
           long sA, long sBout, long sBin, int inB,
           long oCout, long oCin, int inC,
           float alpha, int relu, int rnd) {
    constexpr int TN = NIN * 32;
    constexpr int STG_FLOATS = (TILE_M + TN) * KSTR;
    extern __shared__ __align__(16) float smem[];
    uint32_t smemBase = smem_u32(smem);
    const uint32_t STG_BYTES = STG_FLOATS * 4;
    const uint32_t AB_OFF = TILE_M * KSTR * 4;

    int tid = threadIdx.x;
    int lane = tid & 31;
    int wid = tid >> 5;
    int wm = (wid & 1) * 64;           // warp m offset
    int wn = (wid >> 1) * (NIN * 8);   // warp n offset
    int g = lane >> 2, t = lane & 3;
    int z = blockIdx.z;

    const float* Ab = A + (long)blockIdx.y * TILE_M * lda + (long)z * sA;
    const float* Bb = B + (long)blockIdx.x * TN * ldb
                        + (long)(z / inB) * sBout + (long)(z % inB) * sBin;
    float* Cb = C + (long)(z / inC) * oCout + (long)(z % inC) * oCin
                  + (long)blockIdx.y * TILE_M * ldc + (long)blockIdx.x * TN;

    float acc[4][NIN][4];
#pragma unroll
    for (int i = 0; i < 4; i++)
#pragma unroll
        for (int j = 0; j < NIN; j++)
#pragma unroll
            for (int r = 0; r < 4; r++) acc[i][j][r] = 0.f;

    int nch = K / TILE_K;
    // prologue: stages 0,1
    issue_chunk<NIN>(Ab, Bb, lda, ldb, 0, smemBase, smemBase + AB_OFF, tid);
    issue_chunk<NIN>(Ab, Bb, lda, ldb, TILE_K,
                     smemBase + STG_BYTES, smemBase + STG_BYTES + AB_OFF, tid);

    uint32_t af[2][4][4];
    uint32_t bf[2][NIN][2];

    int stC = 0;   // compute stage for chunk c
    int stI = 2;   // issue stage for chunk c+2
    for (int c = 0; c < nch; c++) {
        CP_WAIT1();            // chunk c resident
        __syncthreads();       // visible to all warps; prior reads of stI done
        if (c + 2 < nch) {
            uint32_t sb = smemBase + (uint32_t)stI * STG_BYTES;
            issue_chunk<NIN>(Ab, Bb, lda, ldb, (c + 2) * TILE_K,
                             sb, sb + AB_OFF, tid);
        }
        const float* As = smem + stC * STG_FLOATS;
        const float* Bs = As + TILE_M * KSTR;
        // fragment pipeline: prime ks=0, then load ks+1 while MMA ks
        load_frags<NIN>(As, Bs, 0, wm, wn, g, t, af[0], bf[0]);
#pragma unroll
        for (int ks = 0; ks < 4; ks++) {
            int cur = ks & 1;
            if (ks < 3)
                load_frags<NIN>(As, Bs, (ks + 1) * 8, wm, wn, g, t,
                                af[cur ^ 1], bf[cur ^ 1]);
#pragma unroll
            for (int im = 0; im < 4; im++)
#pragma unroll
                for (int in = 0; in < NIN; in++)
                    mma_tf32(acc[im][in], af[cur][im], bf[cur][in]);
        }
        stC++; if (stC == STAGES) stC = 0;
        stI++; if (stI == STAGES) stI = 0;
    }

    // epilogue
    int nBase = blockIdx.x * TN;
#pragma unroll
    for (int im = 0; im < 4; im++) {
#pragma unroll
        for (int in = 0; in < NIN; in++) {
            int r0 = wm + im * 16 + g;
            int cn = wn + in * 8 + t * 2;
            float2 v0, v1;
            v0.x = acc[im][in][0] * alpha;
            v0.y = acc[im][in][1] * alpha;
            v1.x = acc[im][in][2] * alpha;
            v1.y = acc[im][in][3] * alpha;
            if (bias) {
                float bx = bias[nBase + cn], by = bias[nBase + cn + 1];
                v0.x += bx; v0.y += by;
                v1.x += bx; v1.y += by;
            }
            if (relu) {
                v0.x = fmaxf(v0.x, 0.f); v0.y = fmaxf(v0.y, 0.f);
                v1.x = fmaxf(v1.x, 0.f); v1.y = fmaxf(v1.y, 0.f);
            }
            if (rnd) {
                v0.x = tf32r(v0.x); v0.y = tf32r(v0.y);
                v1.x = tf32r(v1.x); v1.y = tf32r(v1.y);
            }
            *(float2*)&Cb[(long)r0 * ldc + cn] = v0;
            *(float2*)&Cb[(long)(r0 + 8) * ldc + cn] = v1;
        }
    }
}

#define SMEM4 (STAGES * (TILE_M + 128) * KSTR * 4)   // 110592
#define SMEM8 (STAGES * (TILE_M + 256) * KSTR * 4)   // 165888

// ===========================================================================
// Transpose + tf32 round: out[z, c, r] = tf32(in[z, r, c]).
// ===========================================================================
__global__ void transpose_kernel(const float* __restrict__ in,
                                 float* __restrict__ out, int R, int C) {
    __shared__ float t[32][33];
    long zoff = (long)blockIdx.z * R * C;
    int c0 = blockIdx.x * 32, r0 = blockIdx.y * 32;
    int x = threadIdx.x, y = threadIdx.y;
#pragma unroll
    for (int j = 0; j < 32; j += 8)
        t[y + j][x] = in[zoff + (long)(r0 + y + j) * C + c0 + x];
    __syncthreads();
#pragma unroll
    for (int j = 0; j < 32; j += 8)
        out[zoff + (long)(c0 + y + j) * R + r0 + x] = tf32r(t[x][y + j]);
}

// ===========================================================================
// Embedding: x full + xr (tf32-rounded copy)
// ===========================================================================
__global__ void embed_kernel(const int* __restrict__ idx,
                             const float* __restrict__ tok,
                             const float* __restrict__ pos,
                             float* __restrict__ x,
                             float* __restrict__ xr) {
    int row = blockIdx.x;
    int t = row % Tq;
    int v = idx[row];
    const float4* te = (const float4*)(tok + (long)v * Dq);
    const float4* pe = (const float4*)(pos + (long)t * Dq);
    float4* xo = (float4*)(x + (long)row * Dq);
    float4* xro = (float4*)(xr + (long)row * Dq);
    for (int i = threadIdx.x; i < Dq / 4; i += blockDim.x) {
        float4 a = te[i], b = pe[i];
        float4 v4 = make_float4(a.x + b.x, a.y + b.y, a.z + b.z, a.w + b.w);
        xo[i] = v4;
        xro[i] = make_float4(tf32r(v4.x), tf32r(v4.y), tf32r(v4.z), tf32r(v4.w));
    }
}

// ===========================================================================
// Row softmax over 1024 cols, in place, output tf32-rounded (feeds PV GEMM).
// ===========================================================================
__global__ void softmax_kernel(float* __restrict__ S) {
    __shared__ float sred[8];
    float* p = S + (long)blockIdx.x * Tq;
    int tid = threadIdx.x;
    float4 v = ((const float4*)p)[tid];

    float m = fmaxf(fmaxf(v.x, v.y), fmaxf(v.z, v.w));
#pragma unroll
    for (int o = 16; o; o >>= 1) m = fmaxf(m, __shfl_xor_sync(0xffffffffu, m, o));
    if ((tid & 31) == 0) sred[tid >> 5] = m;
    __syncthreads();
    if (tid < 32) {
        float t = (tid < 8) ? sred[tid] : -1e30f;
#pragma unroll
        for (int o = 16; o; o >>= 1) t = fmaxf(t, __shfl_xor_sync(0xffffffffu, t, o));
        if (tid == 0) sred[0] = t;
    }
    __syncthreads();
    m = sred[0];
    __syncthreads();

    v.x = __expf(v.x - m); v.y = __expf(v.y - m);
    v.z = __expf(v.z - m); v.w = __expf(v.w - m);
    float s = v.x + v.y + v.z + v.w;
#pragma unroll
    for (int o = 16; o; o >>= 1) s += __shfl_xor_sync(0xffffffffu, s, o);
    if ((tid & 31) == 0) sred[tid >> 5] = s;
    __syncthreads();
    if (tid < 32) {
        float t = (tid < 8) ? sred[tid] : 0.f;
#pragma unroll
        for (int o = 16; o; o >>= 1) t += __shfl_xor_sync(0xffffffffu, t, o);
        if (tid == 0) sred[0] = t;
    }
    __syncthreads();
    float inv = 1.0f / sred[0];
    v.x = tf32r(v.x * inv); v.y = tf32r(v.y * inv);
    v.z = tf32r(v.z * inv); v.w = tf32r(v.w * inv);
    ((float4*)p)[tid] = v;
}

// ===========================================================================
// out = LayerNorm(a + b) * g + be.
// ===========================================================================
__global__ void add_ln_kernel(const float* __restrict__ a,
                              const float* __restrict__ b,
                              const float* __restrict__ g,
                              const float* __restrict__ be,
                              float* __restrict__ out,
                              float* __restrict__ outR,
                              int roundMain) {
    __shared__ float sred[4];
    int row = blockIdx.x;
    int tid = threadIdx.x;  // 128
    float4 va = ((const float4*)(a + (long)row * Dq))[tid];
    float4 vb = ((const float4*)(b + (long)row * Dq))[tid];
    float4 v = make_float4(va.x + vb.x, va.y + vb.y, va.z + vb.z, va.w + vb.w);

    float s = v.x + v.y + v.z + v.w;
#pragma unroll
    for (int o = 16; o; o >>= 1) s += __shfl_xor_sync(0xffffffffu, s, o);
    if ((tid & 31) == 0) sred[tid >> 5] = s;
    __syncthreads();
    float mean = (sred[0] + sred[1] + sred[2] + sred[3]) * (1.0f / Dq);
    __syncthreads();

    float dx = v.x - mean, dy = v.y - mean, dz = v.z - mean, dw = v.w - mean;
    float sq = dx * dx + dy * dy + dz * dz + dw * dw;
#pragma unroll
    for (int o = 16; o; o >>= 1) sq += __shfl_xor_sync(0xffffffffu, sq, o);
    if ((tid & 31) == 0) sred[tid >> 5] = sq;
    __syncthreads();
    float var = (sred[0] + sred[1] + sred[2] + sred[3]) * (1.0f / Dq);
    float inv = rsqrtf(var + 1e-5f);

    float4 gg = ((const float4*)g)[tid];
    float4 bb = ((const float4*)be)[tid];
    float4 r;
    r.x = dx * inv * gg.x + bb.x;
    r.y = dy * inv * gg.y + bb.y;
    r.z = dz * inv * gg.z + bb.z;
    r.w = dw * inv * gg.w + bb.w;
    if (roundMain) {
        r.x = tf32r(r.x); r.y = tf32r(r.y);
        r.z = tf32r(r.z); r.w = tf32r(r.w);
    }
    ((float4*)(out + (long)row * Dq))[tid] = r;
    if (outR) {
        float4 rr = make_float4(tf32r(r.x), tf32r(r.y), tf32r(r.z), tf32r(r.w));
        ((float4*)(outR + (long)row * Dq))[tid] = rr;
    }
}

// ===========================================================================
extern "C" void kernel_launch(void* const* d_in, const int* in_sizes, int n_in,
                              void* d_out, int out_size) {
    const int*   idx  = (const int*)  d_in[0];
    const float* tok  = (const float*)d_in[1];
    const float* pos  = (const float*)d_in[2];
    const float* Wq   = (const float*)d_in[3];
    const float* Wk   = (const float*)d_in[4];
    const float* Wv   = (const float*)d_in[5];
    const float* Wo   = (const float*)d_in[6];
    const float* bo   = (const float*)d_in[7];
    const float* ln1g = (const float*)d_in[8];
    const float* ln1b = (const float*)d_in[9];
    const float* ln2g = (const float*)d_in[10];
    const float* ln2b = (const float*)d_in[11];
    const float* W1   = (const float*)d_in[12];
    const float* b1   = (const float*)d_in[13];
    const float* W2   = (const float*)d_in[14];
    const float* b2   = (const float*)d_in[15];
    const float* lmw  = (const float*)d_in[16];
    const float* lmb  = (const float*)d_in[17];
    float* out = (float*)d_out;

    float *x, *xr, *h, *f, *t, *q, *k, *vt, *s, *o;
    float *wqT, *wkT, *wvT, *woT, *w1T, *w2T, *lmwT;
    cudaGetSymbolAddress((void**)&x, g_x);
    cudaGetSymbolAddress((void**)&xr, g_xr);
    cudaGetSymbolAddress((void**)&h, g_h);
    cudaGetSymbolAddress((void**)&f, g_f);
    cudaGetSymbolAddress((void**)&t, g_t);
    cudaGetSymbolAddress((void**)&q, g_q);
    cudaGetSymbolAddress((void**)&k, g_k);
    cudaGetSymbolAddress((void**)&vt, g_vt);
    cudaGetSymbolAddress((void**)&s, g_s);
    cudaGetSymbolAddress((void**)&o, g_o);
    cudaGetSymbolAddress((void**)&wqT, g_wqT);
    cudaGetSymbolAddress((void**)&wkT, g_wkT);
    cudaGetSymbolAddress((void**)&wvT, g_wvT);
    cudaGetSymbolAddress((void**)&woT, g_woT);
    cudaGetSymbolAddress((void**)&w1T, g_w1T);
    cudaGetSymbolAddress((void**)&w2T, g_w2T);
    cudaGetSymbolAddress((void**)&lmwT, g_lmwT);

    cudaFuncSetAttribute(tgemm<4>, cudaFuncAttributeMaxDynamicSharedMemorySize, SMEM4);
    cudaFuncSetAttribute(tgemm<8>, cudaFuncAttributeMaxDynamicSharedMemorySize, SMEM8);

    const float scale = 1.0f / sqrtf((float)DHq);
    dim3 tb(32, 8);

    // Launch order note: launches 0-3 are the QKV weight transposes + embed;
    // launches 4,5 are tgemm<8> (ncu -s 5 -c 1 profiles launch 5 = K GEMM).
    transpose_kernel<<<dim3(DHq/32, Dq/32, Lq*Hq), tb>>>(Wq, wqT, Dq, DHq);   // 0
    transpose_kernel<<<dim3(DHq/32, Dq/32, Lq*Hq), tb>>>(Wk, wkT, Dq, DHq);   // 1
    transpose_kernel<<<dim3(DHq/32, Dq/32, Lq*Hq), tb>>>(Wv, wvT, Dq, DHq);   // 2
    embed_kernel<<<Nrows, 128>>>(idx, tok, pos, x, xr);                        // 3

    bool first = true;
    for (int l = 0; l < Lq; l++) {
        const float* wqTl = wqT + (long)l * Hq * Dq * DHq;
        const float* wkTl = wkT + (long)l * Hq * Dq * DHq;
        const float* wvTl = wvT + (long)l * Hq * Dq * DHq;
        const float* woTl = woT + (long)l * Dq * Hq * DHq;

        // Q[h] = xr @ WqT[h]^T     (M=4096, N=512, K=512, batch h) -> rounded
        dim3 gq(DHq / 256, Nrows / TILE_M, Hq);
        tgemm<8><<<gq, 256, SMEM8>>>(xr, wqTl, nullptr, q,                     // 4
            Dq, Dq, Dq, DHq,
            0L, (long)Dq * DHq, 0L, 1,
            (long)Nrows * DHq, 0L, 1, 1.0f, 0, 1);
        tgemm<8><<<gq, 256, SMEM8>>>(xr, wkTl, nullptr, k,                     // 5 (profiled)
            Dq, Dq, Dq, DHq,
            0L, (long)Dq * DHq, 0L, 1,
            (long)Nrows * DHq, 0L, 1, 1.0f, 0, 1);

        if (first) {
            // remaining weight transposes (needed before their first use)
            transpose_kernel<<<dim3(Dq/32, (Hq*DHq)/32, Lq), tb>>>(Wo, woT, Hq*DHq, Dq);
            transpose_kernel<<<dim3(Dq/32, Dq/32, Lq), tb>>>(W1, w1T, Dq, Dq);
            transpose_kernel<<<dim3(Dq/32, Dq/32, Lq), tb>>>(W2, w2T, Dq, Dq);
            transpose_kernel<<<dim3(Vq/32, Dq/32, 1), tb>>>(lmw, lmwT, Dq, Vq);
            first = false;
        }

        // Vt[h] = WvT[h] @ xr^T    (M=DH=512, N=B*T=4096, K=512) -> rounded
        dim3 gv(Nrows / 256, DHq / TILE_M, Hq);
        tgemm<8><<<gv, 256, SMEM8>>>(wvTl, xr, nullptr, vt,
            Dq, Dq, Dq, Nrows,
            (long)Dq * DHq, 0L, 0L, 1,
            (long)DHq * Nrows, 0L, 1, 1.0f, 0, 1);

        // scores = scale * Q @ K^T  (M=N=1024, K=512, batch z=h*B+b)
        dim3 gs(Tq / 256, Tq / TILE_M, Hq * Bq);
        tgemm<8><<<gs, 256, SMEM8>>>(q, k, nullptr, s,
            DHq, DHq, DHq, Tq,
            (long)Tq * DHq, (long)Tq * DHq, 0L, 1,
            (long)Tq * Tq, 0L, 1, scale, 0, 0);

        softmax_kernel<<<Hq * Bq * Tq, 256>>>(s);

        // O = P @ Vt^T  (M=T=1024, N=DH=512, K=T=1024) -> concat, rounded
        dim3 gp(DHq / 256, Tq / TILE_M, Hq * Bq);
        tgemm<8><<<gp, 256, SMEM8>>>(s, vt, nullptr, o,
            Tq, Tq, Nrows, Hq * DHq,
            (long)Tq * Tq, (long)DHq * Nrows, (long)Tq, Bq,
            (long)DHq, (long)Tq * Hq * DHq, Bq, 1.0f, 0, 1);

        // attn_out = O @ WoT^T + bo   (narrow N, unbatched -> 128-wide tile)
        dim3 gw(Dq / 128, Nrows / TILE_M, 1);
        tgemm<4><<<gw, 256, SMEM4>>>(o, woTl, bo + (long)l * Dq, t,
            Hq * DHq, Hq * DHq, Hq * DHq, Dq,
            0L, 0L, 0L, 1, 0L, 0L, 1, 1.0f, 0, 0);

        // h = LN(attn_out + x), rounded (feeds only W1 GEMM)
        add_ln_kernel<<<Nrows, 128>>>(t, x, ln1g + (long)l * Dq,
                                      ln1b + (long)l * Dq, h, nullptr, 1);

        tgemm<4><<<gw, 256, SMEM4>>>(h, w1T + (long)l * Dq * Dq,
            b1 + (long)l * Dq, f,
            Dq, Dq, Dq, Dq, 0L, 0L, 0L, 1, 0L, 0L, 1, 1.0f, 1, 1);
        tgemm<4><<<gw, 256, SMEM4>>>(f, w2T + (long)l * Dq * Dq,
            b2 + (long)l * Dq, t,
            Dq, Dq, Dq, Dq, 0L, 0L, 0L, 1, 0L, 0L, 1, 1.0f, 0, 0);

        // x = LN(ff + x) full + rounded copy xr
        add_ln_kernel<<<Nrows, 128>>>(t, x, ln2g + (long)l * Dq,
                                      ln2b + (long)l * Dq, x, xr, 0);
    }

    // logits = xr @ lmwT^T + lmb   (M=4096, N=32000, K=512)
    dim3 glm(Vq / 256, Nrows / TILE_M, 1);
    tgemm<8><<<glm, 256, SMEM8>>>(xr, lmwT, lmb, out,
        Dq, Dq, Dq, Vq, 0L, 0L, 0L, 1, 0L, 0L, 1, 1.0f, 0, 0);
}

// round 10
// speedup vs baseline: 6.4352x; 1.7510x over previous
#include <cuda_runtime.h>
#include <cuda_fp16.h>
#include <cstdint>
#include <math.h>

#define Bq  4
#define Tq  1024
#define Dq  512
#define Hq  8
#define DHq 512
#define Lq  4
#define Vq  32000
#define Nrows (Bq*Tq)   // 4096

// ---- scratch (device globals; no allocation allowed) ----
__device__ float  g_x[Nrows*Dq];                  // residual (full precision)
__device__ __half g_xh[Nrows*Dq];                 // residual, fp16 copy
__device__ __half g_h[Nrows*Dq];                  // post-LN1 (fp16)
__device__ __half g_f[Nrows*Dq];                  // ffn hidden (fp16)
__device__ float  g_t[Nrows*Dq];                  // attn_out / ffn out (fp32)
__device__ __half g_q[Hq*Nrows*DHq];              // [H,B*T,DH]
__device__ __half g_k[Hq*Nrows*DHq];              // [H,B*T,DH]
__device__ __half g_vt[Hq*(size_t)DHq*Nrows];     // [H,DH,B*T]
__device__ float  g_s[(size_t)Hq*Bq*Tq*Tq];       // [H*B,T,T] scores (fp32)
__device__ __half g_p[(size_t)Hq*Bq*Tq*Tq];       // [H*B,T,T] probs (fp16)
__device__ __half g_o[(size_t)Nrows*Hq*DHq];      // [B,T,H*DH]
// transposed weights, fp16 (K-major NT operands everywhere)
__device__ __half g_wqT[Lq*Hq*Dq*DHq];            // [L,H,DH,D]
__device__ __half g_wkT[Lq*Hq*Dq*DHq];
__device__ __half g_wvT[Lq*Hq*Dq*DHq];
__device__ __half g_woT[Lq*Dq*Hq*DHq];            // [L,D,H*DH]
__device__ __half g_w1T[Lq*Dq*Dq];
__device__ __half g_w2T[Lq*Dq*Dq];
__device__ __half g_lmwT[(size_t)Vq*Dq];          // [V,D]

// ===========================================================================
// helpers
// ===========================================================================
__device__ __forceinline__ void mma_f16(float* d, const uint32_t* a,
                                        const uint32_t* b) {
    asm volatile(
        "mma.sync.aligned.m16n8k16.row.col.f32.f16.f16.f32 "
        "{%0,%1,%2,%3}, {%4,%5,%6,%7}, {%8,%9}, {%0,%1,%2,%3};"
        : "+f"(d[0]), "+f"(d[1]), "+f"(d[2]), "+f"(d[3])
        : "r"(a[0]), "r"(a[1]), "r"(a[2]), "r"(a[3]), "r"(b[0]), "r"(b[1]));
}
__device__ __forceinline__ uint32_t smem_u32(const void* p) {
    uint32_t a;
    asm("{ .reg .u64 t; cvta.to.shared.u64 t, %1; cvt.u32.u64 %0, t; }"
        : "=r"(a) : "l"(p));
    return a;
}
#define CP_ASYNC16(dst, src) \
    asm volatile("cp.async.cg.shared.global [%0], [%1], 16;" \
                 :: "r"(dst), "l"(src))
#define CP_COMMIT() asm volatile("cp.async.commit_group;" ::: "memory")
#define CP_WAIT1()  asm volatile("cp.async.wait_group 1;" ::: "memory")

// ===========================================================================
// FP16 HMMA GEMM:  C[M,N] = alpha * A[M,K] @ B[N,K]^T (+bias) (+relu)
//   A,B fp16 row-major (K contiguous), C fp32 or fp16 (outHalf).
//   CTA tile 128 x (NIN*32); 8 warps: 2(m) x 4(n); warp tile 64 x (NIN*8).
//   K chunk 64 halves (128B/row); cp.async 3-stage pipeline.
//   batch z: A += z*sA; B += (z/inB)*sBout + (z%inB)*sBin;
//            C += (z/inC)*oCout + (z%inC)*oCin   (element offsets)
//   M%128==0, N%(NIN*32)==0, K%64==0.
// ===========================================================================
#define TILE_M 128
#define TILE_K 64     // halves per chunk
#define KSTR2  72     // smem row stride in halves (144B) -> conflict-free
#define STAGES 3

template <int NIN>
__device__ __forceinline__ void issue_chunk(const __half* __restrict__ Ab,
                                            const __half* __restrict__ Bb,
                                            int lda, int ldb, int k0,
                                            uint32_t stA, uint32_t stB, int tid) {
#pragma unroll
    for (int j = 0; j < 4; j++) {                  // A: 128 rows x 8 chunks
        int idx = tid + 256 * j;
        int row = idx >> 3, c8 = idx & 7;
        uint32_t dst = stA + (uint32_t)(row * KSTR2 + c8 * 8) * 2u;
        CP_ASYNC16(dst, Ab + (long)row * lda + k0 + c8 * 8);
    }
#pragma unroll
    for (int j = 0; j < NIN; j++) {                // B: TN rows x 8 chunks
        int idx = tid + 256 * j;
        int row = idx >> 3, c8 = idx & 7;
        uint32_t dst = stB + (uint32_t)(row * KSTR2 + c8 * 8) * 2u;
        CP_ASYNC16(dst, Bb + (long)row * ldb + k0 + c8 * 8);
    }
    CP_COMMIT();
}

template <int NIN>
__global__ __launch_bounds__(256, 1)
void hgemm(const __half* __restrict__ A, const __half* __restrict__ B,
           const float* __restrict__ bias, void* __restrict__ Cv,
           int K, int lda, int ldb, int ldc,
           long sA, long sBout, long sBin, int inB,
           long oCout, long oCin, int inC,
           float alpha, int relu, int outHalf) {
    constexpr int TN = NIN * 32;
    constexpr int STG_HALVES = (TILE_M + TN) * KSTR2;
    extern __shared__ __align__(16) __half smem[];
    uint32_t smemBase = smem_u32(smem);
    const uint32_t STG_BYTES = STG_HALVES * 2;
    const uint32_t AB_OFF = TILE_M * KSTR2 * 2;

    int tid = threadIdx.x;
    int lane = tid & 31;
    int wid = tid >> 5;
    int wm = (wid & 1) * 64;           // warp m offset
    int wn = (wid >> 1) * (NIN * 8);   // warp n offset
    int g = lane >> 2, t = lane & 3;
    int z = blockIdx.z;

    const __half* Ab = A + (long)blockIdx.y * TILE_M * lda + (long)z * sA;
    const __half* Bb = B + (long)blockIdx.x * TN * ldb
                         + (long)(z / inB) * sBout + (long)(z % inB) * sBin;
    long cOff = (long)(z / inC) * oCout + (long)(z % inC) * oCin
              + (long)blockIdx.y * TILE_M * ldc + (long)blockIdx.x * TN;

    float acc[4][NIN][4];
#pragma unroll
    for (int i = 0; i < 4; i++)
#pragma unroll
        for (int j = 0; j < NIN; j++)
#pragma unroll
            for (int r = 0; r < 4; r++) acc[i][j][r] = 0.f;

    int nch = K / TILE_K;
    issue_chunk<NIN>(Ab, Bb, lda, ldb, 0, smemBase, smemBase + AB_OFF, tid);
    issue_chunk<NIN>(Ab, Bb, lda, ldb, TILE_K,
                     smemBase + STG_BYTES, smemBase + STG_BYTES + AB_OFF, tid);

    int stC = 0;   // compute stage for chunk c
    int stI = 2;   // issue stage for chunk c+2
    for (int c = 0; c < nch; c++) {
        CP_WAIT1();
        __syncthreads();
        if (c + 2 < nch) {
            uint32_t sb = smemBase + (uint32_t)stI * STG_BYTES;
            issue_chunk<NIN>(Ab, Bb, lda, ldb, (c + 2) * TILE_K,
                             sb, sb + AB_OFF, tid);
        }
        const __half* As = smem + stC * STG_HALVES;
        const __half* Bs = As + TILE_M * KSTR2;
#pragma unroll
        for (int ks = 0; ks < 4; ks++) {           // 4 x k16 steps
            int kk = ks * 16;
            uint32_t af[4][4];
#pragma unroll
            for (int im = 0; im < 4; im++) {
                int row = wm + im * 16 + g;
                int b0 = row * KSTR2 + kk + 2 * t;
                int b1 = (row + 8) * KSTR2 + kk + 2 * t;
                af[im][0] = *(const uint32_t*)(As + b0);
                af[im][1] = *(const uint32_t*)(As + b1);
                af[im][2] = *(const uint32_t*)(As + b0 + 8);
                af[im][3] = *(const uint32_t*)(As + b1 + 8);
            }
            uint32_t bf[NIN][2];
#pragma unroll
            for (int in = 0; in < NIN; in++) {
                int n = wn + in * 8 + g;
                int b0 = n * KSTR2 + kk + 2 * t;
                bf[in][0] = *(const uint32_t*)(Bs + b0);
                bf[in][1] = *(const uint32_t*)(Bs + b0 + 8);
            }
#pragma unroll
            for (int im = 0; im < 4; im++)
#pragma unroll
                for (int in = 0; in < NIN; in++)
                    mma_f16(acc[im][in], af[im], bf[in]);
        }
        stC++; if (stC == STAGES) stC = 0;
        stI++; if (stI == STAGES) stI = 0;
    }

    // epilogue
    int nBase = blockIdx.x * TN;
#pragma unroll
    for (int im = 0; im < 4; im++) {
#pragma unroll
        for (int in = 0; in < NIN; in++) {
            int r0 = wm + im * 16 + g;
            int cn = wn + in * 8 + t * 2;
            float2 v0, v1;
            v0.x = acc[im][in][0] * alpha;
            v0.y = acc[im][in][1] * alpha;
            v1.x = acc[im][in][2] * alpha;
            v1.y = acc[im][in][3] * alpha;
            if (bias) {
                float bx = bias[nBase + cn], by = bias[nBase + cn + 1];
                v0.x += bx; v0.y += by;
                v1.x += bx; v1.y += by;
            }
            if (relu) {
                v0.x = fmaxf(v0.x, 0.f); v0.y = fmaxf(v0.y, 0.f);
                v1.x = fmaxf(v1.x, 0.f); v1.y = fmaxf(v1.y, 0.f);
            }
            if (outHalf) {
                __half* Ch = (__half*)Cv + cOff;
                *(__half2*)&Ch[(long)r0 * ldc + cn] = __floats2half2_rn(v0.x, v0.y);
                *(__half2*)&Ch[(long)(r0 + 8) * ldc + cn] = __floats2half2_rn(v1.x, v1.y);
            } else {
                float* Cf = (float*)Cv + cOff;
                *(float2*)&Cf[(long)r0 * ldc + cn] = v0;
                *(float2*)&Cf[(long)(r0 + 8) * ldc + cn] = v1;
            }
        }
    }
}

#define SMEM4h (STAGES * (TILE_M + 128) * KSTR2 * 2)   // 110592
#define SMEM8h (STAGES * (TILE_M + 256) * KSTR2 * 2)   // 165888

// ===========================================================================
// Transpose + fp16 convert: out[z, c, r] = (half)in[z, r, c].
// ===========================================================================
__global__ void transpose_kernel(const float* __restrict__ in,
                                 __half* __restrict__ out, int R, int C) {
    __shared__ float t[32][33];
    long zoffI = (long)blockIdx.z * R * C;
    int c0 = blockIdx.x * 32, r0 = blockIdx.y * 32;
    int x = threadIdx.x, y = threadIdx.y;
#pragma unroll
    for (int j = 0; j < 32; j += 8)
        t[y + j][x] = in[zoffI + (long)(r0 + y + j) * C + c0 + x];
    __syncthreads();
#pragma unroll
    for (int j = 0; j < 32; j += 8)
        out[zoffI + (long)(c0 + y + j) * R + r0 + x] = __float2half_rn(t[x][y + j]);
}

// ===========================================================================
// Embedding: x full fp32 + xh fp16 copy
// ===========================================================================
__global__ void embed_kernel(const int* __restrict__ idx,
                             const float* __restrict__ tok,
                             const float* __restrict__ pos,
                             float* __restrict__ x,
                             __half* __restrict__ xh) {
    int row = blockIdx.x;
    int t = row % Tq;
    int v = idx[row];
    const float4* te = (const float4*)(tok + (long)v * Dq);
    const float4* pe = (const float4*)(pos + (long)t * Dq);
    float4* xo = (float4*)(x + (long)row * Dq);
    __half2* xho = (__half2*)(xh + (long)row * Dq);
    for (int i = threadIdx.x; i < Dq / 4; i += blockDim.x) {
        float4 a = te[i], b = pe[i];
        float4 v4 = make_float4(a.x + b.x, a.y + b.y, a.z + b.z, a.w + b.w);
        xo[i] = v4;
        xho[i * 2]     = __floats2half2_rn(v4.x, v4.y);
        xho[i * 2 + 1] = __floats2half2_rn(v4.z, v4.w);
    }
}

// ===========================================================================
// Row softmax over 1024 cols: S fp32 in -> P fp16 out.
// ===========================================================================
__global__ void softmax_kernel(const float* __restrict__ S,
                               __half* __restrict__ P) {
    __shared__ float sred[8];
    const float* p = S + (long)blockIdx.x * Tq;
    __half2* po = (__half2*)(P + (long)blockIdx.x * Tq);
    int tid = threadIdx.x;
    float4 v = ((const float4*)p)[tid];

    float m = fmaxf(fmaxf(v.x, v.y), fmaxf(v.z, v.w));
#pragma unroll
    for (int o = 16; o; o >>= 1) m = fmaxf(m, __shfl_xor_sync(0xffffffffu, m, o));
    if ((tid & 31) == 0) sred[tid >> 5] = m;
    __syncthreads();
    if (tid < 32) {
        float t = (tid < 8) ? sred[tid] : -1e30f;
#pragma unroll
        for (int o = 16; o; o >>= 1) t = fmaxf(t, __shfl_xor_sync(0xffffffffu, t, o));
        if (tid == 0) sred[0] = t;
    }
    __syncthreads();
    m = sred[0];
    __syncthreads();

    v.x = __expf(v.x - m); v.y = __expf(v.y - m);
    v.z = __expf(v.z - m); v.w = __expf(v.w - m);
    float s = v.x + v.y + v.z + v.w;
#pragma unroll
    for (int o = 16; o; o >>= 1) s += __shfl_xor_sync(0xffffffffu, s, o);
    if ((tid & 31) == 0) sred[tid >> 5] = s;
    __syncthreads();
    if (tid < 32) {
        float t = (tid < 8) ? sred[tid] : 0.f;
#pragma unroll
        for (int o = 16; o; o >>= 1) t += __shfl_xor_sync(0xffffffffu, t, o);
        if (tid == 0) sred[0] = t;
    }
    __syncthreads();
    float inv = 1.0f / sred[0];
    po[tid * 2]     = __floats2half2_rn(v.x * inv, v.y * inv);
    po[tid * 2 + 1] = __floats2half2_rn(v.z * inv, v.w * inv);
}

// ===========================================================================
// LayerNorm(a + b) * g + be -> optional fp32 out, optional fp16 outH.
// ===========================================================================
__global__ void add_ln_kernel(const float* __restrict__ a,
                              const float* __restrict__ b,
                              const float* __restrict__ g,
                              const float* __restrict__ be,
                              float* __restrict__ out,
                              __half* __restrict__ outH) {
    __shared__ float sred[4];
    int row = blockIdx.x;
    int tid = threadIdx.x;  // 128
    float4 va = ((const float4*)(a + (long)row * Dq))[tid];
    float4 vb = ((const float4*)(b + (long)row * Dq))[tid];
    float4 v = make_float4(va.x + vb.x, va.y + vb.y, va.z + vb.z, va.w + vb.w);

    float s = v.x + v.y + v.z + v.w;
#pragma unroll
    for (int o = 16; o; o >>= 1) s += __shfl_xor_sync(0xffffffffu, s, o);
    if ((tid & 31) == 0) sred[tid >> 5] = s;
    __syncthreads();
    float mean = (sred[0] + sred[1] + sred[2] + sred[3]) * (1.0f / Dq);
    __syncthreads();

    float dx = v.x - mean, dy = v.y - mean, dz = v.z - mean, dw = v.w - mean;
    float sq = dx * dx + dy * dy + dz * dz + dw * dw;
#pragma unroll
    for (int o = 16; o; o >>= 1) sq += __shfl_xor_sync(0xffffffffu, sq, o);
    if ((tid & 31) == 0) sred[tid >> 5] = sq;
    __syncthreads();
    float var = (sred[0] + sred[1] + sred[2] + sred[3]) * (1.0f / Dq);
    float inv = rsqrtf(var + 1e-5f);

    float4 gg = ((const float4*)g)[tid];
    float4 bb = ((const float4*)be)[tid];
    float4 r;
    r.x = dx * inv * gg.x + bb.x;
    r.y = dy * inv * gg.y + bb.y;
    r.z = dz * inv * gg.z + bb.z;
    r.w = dw * inv * gg.w + bb.w;
    if (out)
        ((float4*)(out + (long)row * Dq))[tid] = r;
    if (outH) {
        __half2* ho = (__half2*)(outH + (long)row * Dq);
        ho[tid * 2]     = __floats2half2_rn(r.x, r.y);
        ho[tid * 2 + 1] = __floats2half2_rn(r.z, r.w);
    }
}

// ===========================================================================
extern "C" void kernel_launch(void* const* d_in, const int* in_sizes, int n_in,
                              void* d_out, int out_size) {
    const int*   idx  = (const int*)  d_in[0];
    const float* tok  = (const float*)d_in[1];
    const float* pos  = (const float*)d_in[2];
    const float* Wq   = (const float*)d_in[3];
    const float* Wk   = (const float*)d_in[4];
    const float* Wv   = (const float*)d_in[5];
    const float* Wo   = (const float*)d_in[6];
    const float* bo   = (const float*)d_in[7];
    const float* ln1g = (const float*)d_in[8];
    const float* ln1b = (const float*)d_in[9];
    const float* ln2g = (const float*)d_in[10];
    const float* ln2b = (const float*)d_in[11];
    const float* W1   = (const float*)d_in[12];
    const float* b1   = (const float*)d_in[13];
    const float* W2   = (const float*)d_in[14];
    const float* b2   = (const float*)d_in[15];
    const float* lmw  = (const float*)d_in[16];
    const float* lmb  = (const float*)d_in[17];
    float* out = (float*)d_out;

    float *x, *t, *s;
    __half *xh, *h, *f, *q, *k, *vt, *p, *o;
    __half *wqT, *wkT, *wvT, *woT, *w1T, *w2T, *lmwT;
    cudaGetSymbolAddress((void**)&x, g_x);
    cudaGetSymbolAddress((void**)&xh, g_xh);
    cudaGetSymbolAddress((void**)&h, g_h);
    cudaGetSymbolAddress((void**)&f, g_f);
    cudaGetSymbolAddress((void**)&t, g_t);
    cudaGetSymbolAddress((void**)&q, g_q);
    cudaGetSymbolAddress((void**)&k, g_k);
    cudaGetSymbolAddress((void**)&vt, g_vt);
    cudaGetSymbolAddress((void**)&s, g_s);
    cudaGetSymbolAddress((void**)&p, g_p);
    cudaGetSymbolAddress((void**)&o, g_o);
    cudaGetSymbolAddress((void**)&wqT, g_wqT);
    cudaGetSymbolAddress((void**)&wkT, g_wkT);
    cudaGetSymbolAddress((void**)&wvT, g_wvT);
    cudaGetSymbolAddress((void**)&woT, g_woT);
    cudaGetSymbolAddress((void**)&w1T, g_w1T);
    cudaGetSymbolAddress((void**)&w2T, g_w2T);
    cudaGetSymbolAddress((void**)&lmwT, g_lmwT);

    cudaFuncSetAttribute(hgemm<4>, cudaFuncAttributeMaxDynamicSharedMemorySize, SMEM4h);
    cudaFuncSetAttribute(hgemm<8>, cudaFuncAttributeMaxDynamicSharedMemorySize, SMEM8h);

    const float scale = 1.0f / sqrtf((float)DHq);
    dim3 tb(32, 8);

    // launches 0-3; launch 5 below is hgemm<8> (profiled by ncu -s 5 -c 1)
    transpose_kernel<<<dim3(DHq/32, Dq/32, Lq*Hq), tb>>>(Wq, wqT, Dq, DHq);   // 0
    transpose_kernel<<<dim3(DHq/32, Dq/32, Lq*Hq), tb>>>(Wk, wkT, Dq, DHq);   // 1
    transpose_kernel<<<dim3(DHq/32, Dq/32, Lq*Hq), tb>>>(Wv, wvT, Dq, DHq);   // 2
    embed_kernel<<<Nrows, 128>>>(idx, tok, pos, x, xh);                        // 3

    bool first = true;
    for (int l = 0; l < Lq; l++) {
        const __half* wqTl = wqT + (long)l * Hq * Dq * DHq;
        const __half* wkTl = wkT + (long)l * Hq * Dq * DHq;
        const __half* wvTl = wvT + (long)l * Hq * Dq * DHq;
        const __half* woTl = woT + (long)l * Dq * Hq * DHq;

        // Q[h] = xh @ WqT[h]^T     (M=4096, N=512, K=512, batch h) -> fp16
        dim3 gq(DHq / 256, Nrows / TILE_M, Hq);
        hgemm<8><<<gq, 256, SMEM8h>>>(xh, wqTl, nullptr, q,                    // 4
            Dq, Dq, Dq, DHq,
            0L, (long)Dq * DHq, 0L, 1,
            (long)Nrows * DHq, 0L, 1, 1.0f, 0, 1);
        hgemm<8><<<gq, 256, SMEM8h>>>(xh, wkTl, nullptr, k,                    // 5
            Dq, Dq, Dq, DHq,
            0L, (long)Dq * DHq, 0L, 1,
            (long)Nrows * DHq, 0L, 1, 1.0f, 0, 1);

        if (first) {
            transpose_kernel<<<dim3(Dq/32, (Hq*DHq)/32, Lq), tb>>>(Wo, woT, Hq*DHq, Dq);
            transpose_kernel<<<dim3(Dq/32, Dq/32, Lq), tb>>>(W1, w1T, Dq, Dq);
            transpose_kernel<<<dim3(Dq/32, Dq/32, Lq), tb>>>(W2, w2T, Dq, Dq);
            transpose_kernel<<<dim3(Vq/32, Dq/32, 1), tb>>>(lmw, lmwT, Dq, Vq);
            first = false;
        }

        // Vt[h] = WvT[h] @ xh^T    (M=DH=512, N=B*T=4096, K=512) -> fp16
        dim3 gv(Nrows / 256, DHq / TILE_M, Hq);
        hgemm<8><<<gv, 256, SMEM8h>>>(wvTl, xh, nullptr, vt,
            Dq, Dq, Dq, Nrows,
            (long)Dq * DHq, 0L, 0L, 1,
            (long)DHq * Nrows, 0L, 1, 1.0f, 0, 1);

        // scores = scale * Q @ K^T  (M=N=1024, K=512, batch z=h*B+b) -> fp32
        dim3 gs(Tq / 256, Tq / TILE_M, Hq * Bq);
        hgemm<8><<<gs, 256, SMEM8h>>>(q, k, nullptr, s,
            DHq, DHq, DHq, Tq,
            (long)Tq * DHq, (long)Tq * DHq, 0L, 1,
            (long)Tq * Tq, 0L, 1, scale, 0, 0);

        softmax_kernel<<<Hq * Bq * Tq, 256>>>(s, p);

        // O = P @ Vt^T  (M=T=1024, N=DH=512, K=T=1024) -> concat, fp16
        dim3 gp(DHq / 256, Tq / TILE_M, Hq * Bq);
        hgemm<8><<<gp, 256, SMEM8h>>>(p, vt, nullptr, o,
            Tq, Tq, Nrows, Hq * DHq,
            (long)Tq * Tq, (long)DHq * Nrows, (long)Tq, Bq,
            (long)DHq, (long)Tq * Hq * DHq, Bq, 1.0f, 0, 1);

        // attn_out = O @ WoT^T + bo -> fp32 t
        dim3 gw(Dq / 128, Nrows / TILE_M, 1);
        hgemm<4><<<gw, 256, SMEM4h>>>(o, woTl, bo + (long)l * Dq, t,
            Hq * DHq, Hq * DHq, Hq * DHq, Dq,
            0L, 0L, 0L, 1, 0L, 0L, 1, 1.0f, 0, 0);

        // h = LN(attn_out + x) -> fp16 only
        add_ln_kernel<<<Nrows, 128>>>(t, x, ln1g + (long)l * Dq,
                                      ln1b + (long)l * Dq, nullptr, h);

        hgemm<4><<<gw, 256, SMEM4h>>>(h, w1T + (long)l * Dq * Dq,
            b1 + (long)l * Dq, f,
            Dq, Dq, Dq, Dq, 0L, 0L, 0L, 1, 0L, 0L, 1, 1.0f, 1, 1);
        hgemm<4><<<gw, 256, SMEM4h>>>(f, w2T + (long)l * Dq * Dq,
            b2 + (long)l * Dq, t,
            Dq, Dq, Dq, Dq, 0L, 0L, 0L, 1, 0L, 0L, 1, 1.0f, 0, 0);

        // x = LN(ff + x) -> fp32 x + fp16 xh
        add_ln_kernel<<<Nrows, 128>>>(t, x, ln2g + (long)l * Dq,
                                      ln2b + (long)l * Dq, x, xh);
    }

    // logits = xh @ lmwT^T + lmb   (M=4096, N=32000, K=512) -> fp32 out
    dim3 glm(Vq / 256, Nrows / TILE_M, 1);
    hgemm<8><<<glm, 256, SMEM8h>>>(xh, lmwT, lmb, out,
        Dq, Dq, Dq, Vq, 0L, 0L, 0L, 1, 0L, 0L, 1, 1.0f, 0, 0);
}